// round 1
// baseline (speedup 1.0000x reference)
#include <cuda_runtime.h>
#include <math.h>

#define NBATCH 128
#define CIN    2048
#define COUT   256
#define KNODES 16
#define SPOS   256     // W*H
#define DOUT   512
#define KFC    4096    // KNODES*COUT

// ---------------- device scratch (no allocations allowed) ----------------
__device__ float g_part[NBATCH * 4 * SPOS];          // partial channel sums
__device__ int   g_pos[NBATCH * KNODES];             // gather positions (r*16+c)
__device__ float g_lnorm[NBATCH * KNODES * KNODES];  // normalized adjacency
__device__ float g_x[NBATCH * KNODES * COUT];        // relu(conv) output
__device__ float g_y[NBATCH * KNODES * COUT];        // lnorm @ x
__device__ float g_partial[16 * NBATCH * DOUT];      // k-split FC partials

// ---------------- K1: channel sum (HBM-bound) ----------------
// grid (128, 4), block 256. Each block sums 512 channels for one n.
__global__ void k1_sum(const float* __restrict__ s) {
    int n = blockIdx.x, g = blockIdx.y, pos = threadIdx.x;
    const float* base = s + ((size_t)n * CIN + (size_t)g * 512) * SPOS + pos;
    float a0 = 0.f, a1 = 0.f, a2 = 0.f, a3 = 0.f;
#pragma unroll 4
    for (int c = 0; c < 512; c += 4) {
        a0 += base[(c + 0) * SPOS];
        a1 += base[(c + 1) * SPOS];
        a2 += base[(c + 2) * SPOS];
        a3 += base[(c + 3) * SPOS];
    }
    g_part[(n * 4 + g) * SPOS + pos] = (a0 + a1) + (a2 + a3);
}

// ---------------- K2: top-k (jax semantics: descending, min-index ties) + lnorm ----------------
// grid 128, block 256
__global__ void k2_topk(void) {
    __shared__ float feat[SPOS];
    __shared__ float rval[SPOS];
    __shared__ int   ridx[SPOS];
    __shared__ int   sel[KNODES];
    __shared__ int   rr[KNODES], cc[KNODES];
    __shared__ float Amat[KNODES][KNODES];
    __shared__ float dinv[KNODES];

    int n = blockIdx.x, t = threadIdx.x;
    float f = g_part[(n * 4 + 0) * SPOS + t] + g_part[(n * 4 + 1) * SPOS + t] +
              g_part[(n * 4 + 2) * SPOS + t] + g_part[(n * 4 + 3) * SPOS + t];
    feat[t] = f;
    __syncthreads();

    for (int it = 0; it < KNODES; it++) {
        rval[t] = feat[t];
        ridx[t] = t;
        __syncthreads();
        for (int sstep = 128; sstep > 0; sstep >>= 1) {
            if (t < sstep) {
                float v2 = rval[t + sstep];
                int   i2 = ridx[t + sstep];
                if (v2 > rval[t] || (v2 == rval[t] && i2 < ridx[t])) {
                    rval[t] = v2;
                    ridx[t] = i2;
                }
            }
            __syncthreads();
        }
        if (t == 0) {
            sel[it] = ridx[0];
            feat[ridx[0]] = -3.4e38f;
        }
        __syncthreads();
    }

    if (t < KNODES) {
        int p = sel[t];
        int r = (p < 16) ? 0 : ((p >> 4) - 1);
        int q = p & 15;
        int c = (q == 0) ? 15 : (q - 1);
        rr[t] = r;
        cc[t] = c;
        g_pos[n * KNODES + t] = r * 16 + c;
    }
    __syncthreads();

    {   // adjacency (one pair per thread)
        int i = t >> 4, j = t & 15;
        float dr = (float)(rr[i] - rr[j]);
        float dc = (float)(cc[i] - cc[j]);
        Amat[i][j] = expf(-(dr * dr + dc * dc) / (2.0f * (float)KNODES));
    }
    __syncthreads();
    if (t < KNODES) {
        float s = 0.f;
#pragma unroll
        for (int j = 0; j < KNODES; j++) s += Amat[t][j];
        dinv[t] = 1.0f / sqrtf(s);
    }
    __syncthreads();
    {
        int i = t >> 4, j = t & 15;
        g_lnorm[n * 256 + t] = Amat[i][j] * dinv[i] * dinv[j];
    }
}

// ---------------- K3: fused gather + GEMM1 + bias + relu ----------------
// x[n,k,o] = relu( sum_c sounds[n,c,r_k,c_k] * conv_w[o,c] + conv_b[o] )
// grid (2 out-halves, 64 n-pairs), block 256.
// Block tile: 32 rows (2 n * 16 k) x 128 out-cols. Thread tile 4x4.
__global__ void k3_gemm1(const float* __restrict__ sounds,
                         const float* __restrict__ conv_w,
                         const float* __restrict__ conv_b) {
    __shared__ float As[64][32];   // [c_local][row]  (row = local (n,k))
    __shared__ float Bs[128][65];  // [o_local][c_local], pad 65 -> conflict-free reads
    __shared__ int   spos[32];

    const int tid   = threadIdx.x;
    const int ohalf = blockIdx.x;   // 0..1
    const int npair = blockIdx.y;   // 0..63
    const int n0 = npair * 2;
    const int o0 = ohalf * 128;

    if (tid < 32) {
        int n = n0 + (tid >> 4);
        spos[tid] = g_pos[n * KNODES + (tid & 15)];
    }
    __syncthreads();

    const int warp = tid >> 5, lane = tid & 31;
    const int r0 = warp * 4;  // 8 warps * 4 rows = 32 rows

    float acc[4][4];
#pragma unroll
    for (int i = 0; i < 4; i++)
#pragma unroll
        for (int j = 0; j < 4; j++) acc[i][j] = 0.f;

    for (int c0 = 0; c0 < CIN; c0 += 64) {
        // gather A: 64 channels x 32 rows (uncoalesced by layout)
#pragma unroll
        for (int i = 0; i < 8; i++) {
            int e = tid + 256 * i;
            int cl = e >> 5, row = e & 31;
            int n = n0 + (row >> 4);
            As[cl][row] = sounds[((size_t)n * CIN + c0 + cl) * SPOS + spos[row]];
        }
        // load B: conv_w[o0+o][c0 + 0..63], float4 coalesced
        {
            int c4 = (tid & 15) * 4;
            int ob = tid >> 4;  // 0..15
#pragma unroll
            for (int i = 0; i < 8; i++) {
                int o = ob + 16 * i;  // 0..127
                float4 v = *reinterpret_cast<const float4*>(
                    &conv_w[(size_t)(o0 + o) * CIN + c0 + c4]);
                Bs[o][c4 + 0] = v.x;
                Bs[o][c4 + 1] = v.y;
                Bs[o][c4 + 2] = v.z;
                Bs[o][c4 + 3] = v.w;
            }
        }
        __syncthreads();

#pragma unroll 8
        for (int kk = 0; kk < 64; kk++) {
            float4 av = *reinterpret_cast<const float4*>(&As[kk][r0]);  // warp broadcast
            float a[4] = {av.x, av.y, av.z, av.w};
            float bv[4];
#pragma unroll
            for (int j = 0; j < 4; j++) bv[j] = Bs[lane + 32 * j][kk];
#pragma unroll
            for (int i = 0; i < 4; i++)
#pragma unroll
                for (int j = 0; j < 4; j++) acc[i][j] += a[i] * bv[j];
        }
        __syncthreads();
    }

    // epilogue: bias + relu
#pragma unroll
    for (int i = 0; i < 4; i++) {
        int row = r0 + i;
        int n = n0 + (row >> 4), k = row & 15;
#pragma unroll
        for (int j = 0; j < 4; j++) {
            int o = o0 + lane + 32 * j;
            float v = acc[i][j] + conv_b[o];
            g_x[((size_t)n * KNODES + k) * COUT + o] = fmaxf(v, 0.f);
        }
    }
}

// ---------------- K4: y = lnorm @ x (tiny) ----------------
// grid 128, block 256; thread owns column o = tid across all 16 rows.
__global__ void k4_mix(void) {
    __shared__ float L[256];
    int n = blockIdx.x, t = threadIdx.x;
    L[t] = g_lnorm[n * 256 + t];
    __syncthreads();
    float xv[16];
#pragma unroll
    for (int j = 0; j < 16; j++) xv[j] = g_x[(size_t)n * KFC + j * 256 + t];
#pragma unroll
    for (int i = 0; i < 16; i++) {
        float y = 0.f;
#pragma unroll
        for (int j = 0; j < 16; j++) y += L[i * 16 + j] * xv[j];
        g_y[(size_t)n * KFC + i * 256 + t] = y;
    }
}

// ---------------- K5: FC GEMM, K-split x16 ----------------
// out_partial[ks][n][d] over k-chunk of 256. Block tile: 64 n x 128 d.
// grid 128 = (ks 16) x (dtile 4) x (nhalf 2), block 256, thread tile 8x4.
__global__ void k5_fc(const float* __restrict__ fc_w) {
    __shared__ float As[64][32];   // [n_local][kk]
    __shared__ float Bs[128][33];  // [d_local][kk], pad 33
    int tid = threadIdx.x;
    int b = blockIdx.x;
    int ks = b & 15;
    int dt = (b >> 4) & 3;
    int nh = b >> 6;
    int n0 = nh * 64, d0 = dt * 128, k0 = ks * 256;
    int warp = tid >> 5, lane = tid & 31;
    int nr0 = warp * 8;  // 8 warps * 8 rows = 64

    float acc[8][4];
#pragma unroll
    for (int i = 0; i < 8; i++)
#pragma unroll
        for (int j = 0; j < 4; j++) acc[i][j] = 0.f;

    for (int cc = 0; cc < 256; cc += 32) {
        int kbase = k0 + cc;
#pragma unroll
        for (int i = 0; i < 8; i++) {   // A: 64x32
            int e = tid + 256 * i;
            int nn = e >> 5, kk = e & 31;
            As[nn][kk] = g_y[(size_t)(n0 + nn) * KFC + kbase + kk];
        }
#pragma unroll
        for (int i = 0; i < 16; i++) {  // B: 128x32
            int e = tid + 256 * i;
            int dd = e >> 5, kk = e & 31;
            Bs[dd][kk] = fc_w[(size_t)(d0 + dd) * KFC + kbase + kk];
        }
        __syncthreads();

#pragma unroll 4
        for (int kk = 0; kk < 32; kk++) {
            float av[8];
#pragma unroll
            for (int i = 0; i < 8; i++) av[i] = As[nr0 + i][kk];  // broadcast
            float bv[4];
#pragma unroll
            for (int j = 0; j < 4; j++) bv[j] = Bs[lane + 32 * j][kk];
#pragma unroll
            for (int i = 0; i < 8; i++)
#pragma unroll
                for (int j = 0; j < 4; j++) acc[i][j] += av[i] * bv[j];
        }
        __syncthreads();
    }

#pragma unroll
    for (int i = 0; i < 8; i++)
#pragma unroll
        for (int j = 0; j < 4; j++)
            g_partial[(size_t)ks * (NBATCH * DOUT) + (n0 + nr0 + i) * DOUT + d0 +
                      lane + 32 * j] = acc[i][j];
}

// ---------------- K6: reduce k-splits + bias ----------------
__global__ void k6_reduce(const float* __restrict__ fc_b, float* __restrict__ out) {
    int idx = blockIdx.x * 256 + threadIdx.x;  // 65536 total
    int d = idx & (DOUT - 1);
    float s = fc_b[d];
#pragma unroll
    for (int ks = 0; ks < 16; ks++) s += g_partial[(size_t)ks * (NBATCH * DOUT) + idx];
    out[idx] = s;
}

// ---------------- launch ----------------
extern "C" void kernel_launch(void* const* d_in, const int* in_sizes, int n_in,
                              void* d_out, int out_size) {
    const float* sounds = (const float*)d_in[0];
    const float* conv_w = (const float*)d_in[1];
    const float* conv_b = (const float*)d_in[2];
    const float* fc_w   = (const float*)d_in[3];
    const float* fc_b   = (const float*)d_in[4];
    float* out = (float*)d_out;

    k1_sum<<<dim3(128, 4), 256>>>(sounds);
    k2_topk<<<128, 256>>>();
    k3_gemm1<<<dim3(2, 64), 256>>>(sounds, conv_w, conv_b);
    k4_mix<<<128, 256>>>();
    k5_fc<<<128, 256>>>(fc_w);
    k6_reduce<<<256, 256>>>(fc_b, out);
}

// round 3
// speedup vs baseline: 1.6724x; 1.6724x over previous
#include <cuda_runtime.h>
#include <cstdint>
#include <math.h>

#define NBATCH 128
#define CIN    2048
#define COUT   256
#define KNODES 16
#define SPOS   256     // W*H
#define DOUT   512
#define KFC    4096    // KNODES*COUT

// ---------------- device scratch (no allocations allowed) ----------------
__device__ float g_part[NBATCH * 4 * SPOS];          // partial channel sums
__device__ int   g_pos[NBATCH * KNODES];             // gather positions (r*16+c)
__device__ float g_lnorm[NBATCH * KNODES * KNODES];  // normalized adjacency
__device__ float g_y[NBATCH * KNODES * COUT];        // lnorm @ relu(conv) output
__device__ float g_partial[16 * NBATCH * DOUT];      // k-split FC partials

// ---------------- cp.async helpers ----------------
__device__ __forceinline__ void cp4(void* smem, const void* gmem) {
    unsigned int s = (unsigned int)__cvta_generic_to_shared(smem);
    asm volatile("cp.async.ca.shared.global [%0], [%1], 4;\n" :: "r"(s), "l"(gmem));
}
__device__ __forceinline__ void cp_commit() {
    asm volatile("cp.async.commit_group;\n" ::: "memory");
}
template <int N>
__device__ __forceinline__ void cp_wait() {
    asm volatile("cp.async.wait_group %0;\n" :: "n"(N) : "memory");
}

// ---------------- K1: channel sum (HBM-bound) ----------------
// grid (128, 4), block 256. Each block sums 512 channels for one n.
__global__ void k1_sum(const float* __restrict__ s) {
    int n = blockIdx.x, g = blockIdx.y, pos = threadIdx.x;
    const float* base = s + ((size_t)n * CIN + (size_t)g * 512) * SPOS + pos;
    float a[8];
#pragma unroll
    for (int i = 0; i < 8; i++) a[i] = 0.f;
#pragma unroll 2
    for (int c = 0; c < 512; c += 8) {
#pragma unroll
        for (int i = 0; i < 8; i++) a[i] += base[(c + i) * SPOS];
    }
    float r = ((a[0] + a[1]) + (a[2] + a[3])) + ((a[4] + a[5]) + (a[6] + a[7]));
    g_part[(n * 4 + g) * SPOS + pos] = r;
}

// ---------------- K2: top-k (descending, min-index ties) + lnorm ----------------
// grid 128, block 256
__global__ void k2_topk(void) {
    __shared__ float feat[SPOS];
    __shared__ float rval[SPOS];
    __shared__ int   ridx[SPOS];
    __shared__ int   sel[KNODES];
    __shared__ int   rr[KNODES], cc[KNODES];
    __shared__ float Amat[KNODES][KNODES];
    __shared__ float dinv[KNODES];

    int n = blockIdx.x, t = threadIdx.x;
    float f = g_part[(n * 4 + 0) * SPOS + t] + g_part[(n * 4 + 1) * SPOS + t] +
              g_part[(n * 4 + 2) * SPOS + t] + g_part[(n * 4 + 3) * SPOS + t];
    feat[t] = f;
    __syncthreads();

    for (int it = 0; it < KNODES; it++) {
        rval[t] = feat[t];
        ridx[t] = t;
        __syncthreads();
        for (int sstep = 128; sstep > 0; sstep >>= 1) {
            if (t < sstep) {
                float v2 = rval[t + sstep];
                int   i2 = ridx[t + sstep];
                if (v2 > rval[t] || (v2 == rval[t] && i2 < ridx[t])) {
                    rval[t] = v2;
                    ridx[t] = i2;
                }
            }
            __syncthreads();
        }
        if (t == 0) {
            sel[it] = ridx[0];
            feat[ridx[0]] = -3.4e38f;
        }
        __syncthreads();
    }

    if (t < KNODES) {
        int p = sel[t];
        int r = (p < 16) ? 0 : ((p >> 4) - 1);
        int q = p & 15;
        int c = (q == 0) ? 15 : (q - 1);
        rr[t] = r;
        cc[t] = c;
        g_pos[n * KNODES + t] = r * 16 + c;
    }
    __syncthreads();

    {   // adjacency (one pair per thread)
        int i = t >> 4, j = t & 15;
        float dr = (float)(rr[i] - rr[j]);
        float dc = (float)(cc[i] - cc[j]);
        Amat[i][j] = expf(-(dr * dr + dc * dc) / (2.0f * (float)KNODES));
    }
    __syncthreads();
    if (t < KNODES) {
        float s = 0.f;
#pragma unroll
        for (int j = 0; j < KNODES; j++) s += Amat[t][j];
        dinv[t] = 1.0f / sqrtf(s);
    }
    __syncthreads();
    {
        int i = t >> 4, j = t & 15;
        g_lnorm[n * 256 + t] = Amat[i][j] * dinv[i] * dinv[j];
    }
}

// ---------------- K3: gather + GEMM1 + bias + relu + lnorm-mix (fused) ----------------
// x[n,k,o] = relu( sum_c sounds[n,c,pos_k] * conv_w[o,c] + conv_b[o] )
// y[n,i,o] = sum_j lnorm[n,i,j] * x[n,j,o]
// grid (2 out-halves, 64 n-pairs), block 256.
// Block tile: 32 rows (2 n * 16 k) x 128 out-cols. Thread tile 4x4.
// Double-buffered cp.async pipeline, cin-tile 32.
#define K3_CT 32             // cin tile
#define K3_NT (CIN / K3_CT)  // 64 tiles
__global__ void k3_gemm1(const float* __restrict__ sounds,
                         const float* __restrict__ conv_w,
                         const float* __restrict__ conv_b) {
    __shared__ union {
        struct {
            float As[2][K3_CT][32];   // [c_local][row]
            float Bs[2][128][33];     // [o_local][c_local]
        } p;
        struct {
            float xs[32][132];        // relu(conv) rows
            float L[2][256];          // lnorm for the 2 batch items
        } e;
    } sm;
    __shared__ int spos[32];

    const int tid   = threadIdx.x;
    const int ohalf = blockIdx.x;   // 0..1
    const int npair = blockIdx.y;   // 0..63
    const int n0 = npair * 2;
    const int o0 = ohalf * 128;

    if (tid < 32) {
        int n = n0 + (tid >> 4);
        spos[tid] = g_pos[n * KNODES + (tid & 15)];
    }
    __syncthreads();

    const int warp = tid >> 5, lane = tid & 31;
    const int r0 = warp * 4;  // 8 warps * 4 rows = 32 rows

    // tile loader: gather A (32c x 32row) + B (128o x 32c)
    auto load_tile = [&](int t, int buf) {
        int c0 = t * K3_CT;
        // A: 4 cp4 per thread
#pragma unroll
        for (int i = 0; i < 4; i++) {
            int e = tid + 256 * i;
            int cl = e >> 5, row = e & 31;
            int n = n0 + (row >> 4);
            cp4(&sm.p.As[buf][cl][row],
                &sounds[((size_t)n * CIN + c0 + cl) * SPOS + spos[row]]);
        }
        // B: 16 cp4 per thread (coalesced per warp: same o, consecutive c)
#pragma unroll
        for (int i = 0; i < 16; i++) {
            int e = tid + 256 * i;
            int o = e >> 5, kk = e & 31;
            cp4(&sm.p.Bs[buf][o][kk], &conv_w[(size_t)(o0 + o) * CIN + c0 + kk]);
        }
    };

    float acc[4][4];
#pragma unroll
    for (int i = 0; i < 4; i++)
#pragma unroll
        for (int j = 0; j < 4; j++) acc[i][j] = 0.f;

    load_tile(0, 0);
    cp_commit();

    for (int t = 0; t < K3_NT; t++) {
        int buf = t & 1;
        if (t + 1 < K3_NT) {
            load_tile(t + 1, 1 - buf);
            cp_commit();
            cp_wait<1>();
        } else {
            cp_wait<0>();
        }
        __syncthreads();

#pragma unroll 8
        for (int kk = 0; kk < K3_CT; kk++) {
            float4 av = *reinterpret_cast<const float4*>(&sm.p.As[buf][kk][r0]);
            float a[4] = {av.x, av.y, av.z, av.w};
            float bv[4];
#pragma unroll
            for (int j = 0; j < 4; j++) bv[j] = sm.p.Bs[buf][lane + 32 * j][kk];
#pragma unroll
            for (int i = 0; i < 4; i++)
#pragma unroll
                for (int j = 0; j < 4; j++) acc[i][j] += a[i] * bv[j];
        }
        __syncthreads();
    }

    // epilogue part 1: bias + relu -> smem xs
    float bias[4];
#pragma unroll
    for (int j = 0; j < 4; j++) bias[j] = conv_b[o0 + lane + 32 * j];
#pragma unroll
    for (int i = 0; i < 4; i++) {
        int row = r0 + i;
#pragma unroll
        for (int j = 0; j < 4; j++)
            sm.e.xs[row][lane + 32 * j] = fmaxf(acc[i][j] + bias[j], 0.f);
    }
    // load lnorm for both n
    sm.e.L[0][tid] = g_lnorm[(size_t)n0 * 256 + tid];
    sm.e.L[1][tid] = g_lnorm[(size_t)(n0 + 1) * 256 + tid];
    __syncthreads();

    // epilogue part 2: y = L @ x  (warp's 4 rows share the same n)
    const int nl = r0 >> 4;  // 0 or 1
    float yacc[4][4];
#pragma unroll
    for (int i = 0; i < 4; i++)
#pragma unroll
        for (int j = 0; j < 4; j++) yacc[i][j] = 0.f;
#pragma unroll
    for (int j = 0; j < KNODES; j++) {
        float xv[4];
#pragma unroll
        for (int cj = 0; cj < 4; cj++) xv[cj] = sm.e.xs[nl * 16 + j][lane + 32 * cj];
#pragma unroll
        for (int i = 0; i < 4; i++) {
            int k = (r0 + i) & 15;
            float l = sm.e.L[nl][k * 16 + j];
#pragma unroll
            for (int cj = 0; cj < 4; cj++) yacc[i][cj] += l * xv[cj];
        }
    }
#pragma unroll
    for (int i = 0; i < 4; i++) {
        int k = (r0 + i) & 15;
#pragma unroll
        for (int cj = 0; cj < 4; cj++)
            g_y[((size_t)(n0 + nl) * KNODES + k) * COUT + o0 + lane + 32 * cj] =
                yacc[i][cj];
    }
}

// ---------------- K5: FC GEMM, K-split x16, cp.async double-buffered ----------------
// Block tile: 64 n x 128 d over a k-chunk of 256, k-tile 16.
// grid 128 = (ks 16) x (dtile 4) x (nhalf 2), block 256, thread tile 8x4.
__global__ void k5_fc(const float* __restrict__ fc_w) {
    __shared__ float As[2][64][16];   // [n_local][kk]
    __shared__ float Bs[2][128][17];  // [d_local][kk]
    int tid = threadIdx.x;
    int b = blockIdx.x;
    int ks = b & 15;
    int dt = (b >> 4) & 3;
    int nh = b >> 6;
    int n0 = nh * 64, d0 = dt * 128, k0 = ks * 256;
    int warp = tid >> 5, lane = tid & 31;
    int nr0 = warp * 8;  // 8 warps * 8 rows = 64

    auto load_tile = [&](int t, int buf) {
        int kbase = k0 + t * 16;
#pragma unroll
        for (int i = 0; i < 4; i++) {   // A: 64x16
            int e = tid + 256 * i;
            int nn = e >> 4, kk = e & 15;
            cp4(&As[buf][nn][kk], &g_y[(size_t)(n0 + nn) * KFC + kbase + kk]);
        }
#pragma unroll
        for (int i = 0; i < 8; i++) {   // B: 128x16
            int e = tid + 256 * i;
            int dd = e >> 4, kk = e & 15;
            cp4(&Bs[buf][dd][kk], &fc_w[(size_t)(d0 + dd) * KFC + kbase + kk]);
        }
    };

    float acc[8][4];
#pragma unroll
    for (int i = 0; i < 8; i++)
#pragma unroll
        for (int j = 0; j < 4; j++) acc[i][j] = 0.f;

    load_tile(0, 0);
    cp_commit();

    for (int t = 0; t < 16; t++) {
        int buf = t & 1;
        if (t + 1 < 16) {
            load_tile(t + 1, 1 - buf);
            cp_commit();
            cp_wait<1>();
        } else {
            cp_wait<0>();
        }
        __syncthreads();

#pragma unroll
        for (int kk = 0; kk < 16; kk++) {
            float av[8];
#pragma unroll
            for (int i = 0; i < 8; i++) av[i] = As[buf][nr0 + i][kk];  // broadcast
            float bv[4];
#pragma unroll
            for (int j = 0; j < 4; j++) bv[j] = Bs[buf][lane + 32 * j][kk];
#pragma unroll
            for (int i = 0; i < 8; i++)
#pragma unroll
                for (int j = 0; j < 4; j++) acc[i][j] += av[i] * bv[j];
        }
        __syncthreads();
    }

#pragma unroll
    for (int i = 0; i < 8; i++)
#pragma unroll
        for (int j = 0; j < 4; j++)
            g_partial[(size_t)ks * (NBATCH * DOUT) + (n0 + nr0 + i) * DOUT + d0 +
                      lane + 32 * j] = acc[i][j];
}

// ---------------- K6: reduce k-splits + bias ----------------
__global__ void k6_reduce(const float* __restrict__ fc_b, float* __restrict__ out) {
    int idx = blockIdx.x * 256 + threadIdx.x;  // 65536 total
    int d = idx & (DOUT - 1);
    float s = fc_b[d];
#pragma unroll
    for (int ks = 0; ks < 16; ks++) s += g_partial[(size_t)ks * (NBATCH * DOUT) + idx];
    out[idx] = s;
}

// ---------------- launch ----------------
extern "C" void kernel_launch(void* const* d_in, const int* in_sizes, int n_in,
                              void* d_out, int out_size) {
    const float* sounds = (const float*)d_in[0];
    const float* conv_w = (const float*)d_in[1];
    const float* conv_b = (const float*)d_in[2];
    const float* fc_w   = (const float*)d_in[3];
    const float* fc_b   = (const float*)d_in[4];
    float* out = (float*)d_out;

    k1_sum<<<dim3(128, 4), 256>>>(sounds);
    k2_topk<<<128, 256>>>();
    k3_gemm1<<<dim3(2, 64), 256>>>(sounds, conv_w, conv_b);
    k5_fc<<<128, 256>>>(fc_w);
    k6_reduce<<<256, 256>>>(fc_b, out);
}

// round 4
// speedup vs baseline: 1.8336x; 1.0964x over previous
#include <cuda_runtime.h>
#include <cuda_bf16.h>
#include <cstdint>
#include <math.h>

#define NBATCH 128
#define CIN    2048
#define COUT   256
#define KNODES 16
#define SPOS   256
#define DOUT   512
#define KFC    4096

// ---------------- device scratch ----------------
__device__ float g_part[NBATCH * 4 * SPOS];
__device__ int   g_pos[NBATCH * KNODES];
__device__ float g_lnorm[NBATCH * KNODES * KNODES];
__device__ float g_y[NBATCH * KNODES * COUT];
__device__ float g_partial[16 * NBATCH * DOUT];
__device__ __nv_bfloat16 g_whi[COUT * CIN];      // conv_w hi plane
__device__ __nv_bfloat16 g_wlo[COUT * CIN];      // conv_w lo plane
__device__ float g_xpart[2][2048 * COUT];        // k-split conv partials

// ---------------- async copy helpers ----------------
__device__ __forceinline__ void cp4(void* smem, const void* gmem) {
    unsigned int s = (unsigned int)__cvta_generic_to_shared(smem);
    asm volatile("cp.async.ca.shared.global [%0], [%1], 4;\n" :: "r"(s), "l"(gmem));
}
__device__ __forceinline__ void cp16(void* smem, const void* gmem) {
    unsigned int s = (unsigned int)__cvta_generic_to_shared(smem);
    asm volatile("cp.async.cg.shared.global [%0], [%1], 16;\n" :: "r"(s), "l"(gmem));
}
__device__ __forceinline__ void cp_commit() {
    asm volatile("cp.async.commit_group;\n" ::: "memory");
}
template <int N>
__device__ __forceinline__ void cp_wait() {
    asm volatile("cp.async.wait_group %0;\n" :: "n"(N) : "memory");
}

// ---------------- mma helpers ----------------
__device__ __forceinline__ void mma_bf16(float* c, const unsigned* a, const unsigned* b) {
    asm volatile(
        "mma.sync.aligned.m16n8k16.row.col.f32.bf16.bf16.f32 "
        "{%0,%1,%2,%3},{%4,%5,%6,%7},{%8,%9},{%0,%1,%2,%3};\n"
        : "+f"(c[0]), "+f"(c[1]), "+f"(c[2]), "+f"(c[3])
        : "r"(a[0]), "r"(a[1]), "r"(a[2]), "r"(a[3]), "r"(b[0]), "r"(b[1]));
}
__device__ __forceinline__ void ldsm_x4(unsigned* r, const void* p) {
    unsigned a = (unsigned)__cvta_generic_to_shared(p);
    asm volatile("ldmatrix.sync.aligned.m8n8.x4.shared.b16 {%0,%1,%2,%3}, [%4];\n"
                 : "=r"(r[0]), "=r"(r[1]), "=r"(r[2]), "=r"(r[3]) : "r"(a));
}

// ---------------- K0: split conv_w into bf16 hi/lo planes ----------------
__global__ void k0_prep(const float* __restrict__ conv_w) {
    int i = (blockIdx.x * 256 + threadIdx.x) * 4;
#pragma unroll
    for (int j = 0; j < 4; j++) {
        float w = conv_w[i + j];
        __nv_bfloat16 h = __float2bfloat16_rn(w);
        g_whi[i + j] = h;
        g_wlo[i + j] = __float2bfloat16_rn(w - __bfloat162float(h));
    }
}

// ---------------- K1: channel sum ----------------
__global__ void k1_sum(const float* __restrict__ s) {
    int n = blockIdx.x, g = blockIdx.y, pos = threadIdx.x;
    const float* base = s + ((size_t)n * CIN + (size_t)g * 512) * SPOS + pos;
    float a[8];
#pragma unroll
    for (int i = 0; i < 8; i++) a[i] = 0.f;
#pragma unroll 2
    for (int c = 0; c < 512; c += 8) {
#pragma unroll
        for (int i = 0; i < 8; i++) a[i] += base[(c + i) * SPOS];
    }
    float r = ((a[0] + a[1]) + (a[2] + a[3])) + ((a[4] + a[5]) + (a[6] + a[7]));
    g_part[(n * 4 + g) * SPOS + pos] = r;
}

// ---------------- K2: top-k + lnorm ----------------
__global__ void k2_topk(void) {
    __shared__ float feat[SPOS];
    __shared__ float rval[SPOS];
    __shared__ int   ridx[SPOS];
    __shared__ int   sel[KNODES];
    __shared__ int   rr[KNODES], cc[KNODES];
    __shared__ float Amat[KNODES][KNODES];
    __shared__ float dinv[KNODES];

    int n = blockIdx.x, t = threadIdx.x;
    float f = g_part[(n * 4 + 0) * SPOS + t] + g_part[(n * 4 + 1) * SPOS + t] +
              g_part[(n * 4 + 2) * SPOS + t] + g_part[(n * 4 + 3) * SPOS + t];
    feat[t] = f;
    __syncthreads();

    for (int it = 0; it < KNODES; it++) {
        rval[t] = feat[t];
        ridx[t] = t;
        __syncthreads();
        for (int sstep = 128; sstep > 0; sstep >>= 1) {
            if (t < sstep) {
                float v2 = rval[t + sstep];
                int   i2 = ridx[t + sstep];
                if (v2 > rval[t] || (v2 == rval[t] && i2 < ridx[t])) {
                    rval[t] = v2;
                    ridx[t] = i2;
                }
            }
            __syncthreads();
        }
        if (t == 0) {
            sel[it] = ridx[0];
            feat[ridx[0]] = -3.4e38f;
        }
        __syncthreads();
    }

    if (t < KNODES) {
        int p = sel[t];
        int r = (p < 16) ? 0 : ((p >> 4) - 1);
        int q = p & 15;
        int c = (q == 0) ? 15 : (q - 1);
        rr[t] = r;
        cc[t] = c;
        g_pos[n * KNODES + t] = r * 16 + c;
    }
    __syncthreads();
    {
        int i = t >> 4, j = t & 15;
        float dr = (float)(rr[i] - rr[j]);
        float dc = (float)(cc[i] - cc[j]);
        Amat[i][j] = expf(-(dr * dr + dc * dc) / (2.0f * (float)KNODES));
    }
    __syncthreads();
    if (t < KNODES) {
        float s = 0.f;
#pragma unroll
        for (int j = 0; j < KNODES; j++) s += Amat[t][j];
        dinv[t] = 1.0f / sqrtf(s);
    }
    __syncthreads();
    {
        int i = t >> 4, j = t & 15;
        g_lnorm[n * 256 + t] = Amat[i][j] * dinv[i] * dinv[j];
    }
}

// ---------------- K3: gather + split-bf16 tensor-core GEMM ----------------
// Block: M=32 rows (2 batch x 16 nodes) x N=256, K-chunk 1024 (ksplit in grid.y).
// grid (64 Mtiles, 2 ksplit), 256 threads (8 warps, each warp owns 32 N-cols).
#define KSTEP   32
#define ITERS   32           // 1024 / 32
#define APITCH  40           // bf16 units, 80B rows: 16B-aligned + LDSM conflict-free
#define BPITCH  40
// dyn smem: Bs[2 buf][2 plane][256][BPITCH] bf16 = 81920B, As[2][2][32][APITCH] = 10240B
#define SM_B 0
#define SM_A 81920
#define SMEMSZ (81920 + 10240)

__global__ void __launch_bounds__(256, 1)
k3_gemm1(const float* __restrict__ sounds) {
    extern __shared__ __align__(16) char smraw[];
    __nv_bfloat16* Bsm = (__nv_bfloat16*)(smraw + SM_B);
    __nv_bfloat16* Asm = (__nv_bfloat16*)(smraw + SM_A);
    __shared__ int spos[32];

    const int tid = threadIdx.x;
    const int mt  = blockIdx.x;   // 0..63
    const int ks  = blockIdx.y;   // 0..1
    const int n0  = mt * 2;
    const int kc0 = ks * 1024;

    if (tid < 32) spos[tid] = g_pos[(n0 + (tid >> 4)) * KNODES + (tid & 15)];
    __syncthreads();

    // --- per-thread A gather addressing (4 elements per iter) ---
    size_t abase[4];
    int    aclk[4];
#pragma unroll
    for (int i = 0; i < 4; i++) {
        int e = tid + 256 * i;
        int row = e & 31, cl = e >> 5;
        abase[i] = ((size_t)(n0 + (row >> 4)) * CIN) * SPOS + spos[row];
        aclk[i] = cl;
        // smem dest index (bf16 units, plane 0; plane 1 = +32*APITCH)
    }
    // smem write offsets for A converts
    int asto[4];
#pragma unroll
    for (int i = 0; i < 4; i++) {
        int e = tid + 256 * i;
        int row = e & 31, cl = e >> 5;
        asto[i] = row * APITCH + cl;
    }

    auto ldA = [&](int it, float* r) {
        int c0 = kc0 + it * KSTEP;
#pragma unroll
        for (int i = 0; i < 4; i++)
            r[i] = __ldg(&sounds[abase[i] + (size_t)(c0 + aclk[i]) * SPOS]);
    };
    auto cpB = [&](int it, int buf) {
        int c0 = kc0 + it * KSTEP;
#pragma unroll
        for (int i = 0; i < 8; i++) {
            int q = tid + 256 * i;
            int plane = q >> 10;
            int q2 = q & 1023;
            int n = q2 >> 2, kc = (q2 & 3) * 8;
            const __nv_bfloat16* src =
                (plane ? g_wlo : g_whi) + (size_t)n * CIN + c0 + kc;
            cp16(&Bsm[((buf * 2 + plane) * 256 + n) * BPITCH + kc], src);
        }
    };

    const int warp = tid >> 5, lane = tid & 31;
    const int nb = warp * 32;
    // ldmatrix per-lane offsets (bf16 units)
    const int aRow = lane & 15, aCol = (lane >> 4) * 8;
    const int bRow = (lane & 7) + ((lane >> 4) & 1) * 8;
    const int bCol = ((lane >> 3) & 1) * 8;

    float acc[2][4][4];
#pragma unroll
    for (int mi = 0; mi < 2; mi++)
#pragma unroll
        for (int nj = 0; nj < 4; nj++)
#pragma unroll
            for (int v = 0; v < 4; v++) acc[mi][nj][v] = 0.f;

    float areg[2][4];
    ldA(0, areg[0]);
    ldA(1, areg[1]);
    cpB(0, 0);
    cp_commit();

    for (int it = 0; it < ITERS; it++) {
        const int buf = it & 1;
        // convert A(it) -> smem planes [buf]
        {
            float* r = areg[it & 1];
            __nv_bfloat16* Ah = Asm + (buf * 2 + 0) * 32 * APITCH;
            __nv_bfloat16* Al = Asm + (buf * 2 + 1) * 32 * APITCH;
#pragma unroll
            for (int i = 0; i < 4; i++) {
                __nv_bfloat16 h = __float2bfloat16_rn(r[i]);
                Ah[asto[i]] = h;
                Al[asto[i]] = __float2bfloat16_rn(r[i] - __bfloat162float(h));
            }
        }
        if (it + 2 < ITERS) ldA(it + 2, areg[it & 1]);
        cp_wait<0>();          // B(it) landed
        __syncthreads();       // mma(it-1) done everywhere; A converts visible
        if (it + 1 < ITERS) {
            cpB(it + 1, 1 - buf);
            cp_commit();
        }

        // --- mma over 2 k16 substeps ---
        const __nv_bfloat16* Ah = Asm + (buf * 2 + 0) * 32 * APITCH;
        const __nv_bfloat16* Al = Asm + (buf * 2 + 1) * 32 * APITCH;
        const __nv_bfloat16* Bh = Bsm + (buf * 2 + 0) * 256 * BPITCH;
        const __nv_bfloat16* Bl = Bsm + (buf * 2 + 1) * 256 * BPITCH;
#pragma unroll
        for (int s16 = 0; s16 < 32; s16 += 16) {
            unsigned ah[2][4], al[2][4], bh[2][4], bl[2][4];
            ldsm_x4(ah[0], &Ah[aRow * APITCH + s16 + aCol]);
            ldsm_x4(ah[1], &Ah[(16 + aRow) * APITCH + s16 + aCol]);
            ldsm_x4(al[0], &Al[aRow * APITCH + s16 + aCol]);
            ldsm_x4(al[1], &Al[(16 + aRow) * APITCH + s16 + aCol]);
            ldsm_x4(bh[0], &Bh[(nb + bRow) * BPITCH + s16 + bCol]);
            ldsm_x4(bh[1], &Bh[(nb + 16 + bRow) * BPITCH + s16 + bCol]);
            ldsm_x4(bl[0], &Bl[(nb + bRow) * BPITCH + s16 + bCol]);
            ldsm_x4(bl[1], &Bl[(nb + 16 + bRow) * BPITCH + s16 + bCol]);
#pragma unroll
            for (int mi = 0; mi < 2; mi++) {
#pragma unroll
                for (int nj = 0; nj < 4; nj++) {
                    const unsigned* bhf = &bh[nj >> 1][(nj & 1) * 2];
                    const unsigned* blf = &bl[nj >> 1][(nj & 1) * 2];
                    mma_bf16(acc[mi][nj], ah[mi], bhf);
                    mma_bf16(acc[mi][nj], ah[mi], blf);
                    mma_bf16(acc[mi][nj], al[mi], bhf);
                }
            }
        }
    }

    // --- write fp32 partials ---
    {
        int r = lane >> 2, cq = (lane & 3) * 2;
        float* dst = g_xpart[ks];
#pragma unroll
        for (int mi = 0; mi < 2; mi++) {
#pragma unroll
            for (int nj = 0; nj < 4; nj++) {
                int row0 = mt * 32 + mi * 16 + r;
                int col = nb + nj * 8 + cq;
                *(float2*)&dst[(size_t)row0 * COUT + col] =
                    make_float2(acc[mi][nj][0], acc[mi][nj][1]);
                *(float2*)&dst[(size_t)(row0 + 8) * COUT + col] =
                    make_float2(acc[mi][nj][2], acc[mi][nj][3]);
            }
        }
    }
}

// ---------------- K3b: sum splits + bias + relu + lnorm mix ----------------
__global__ void k3b_mix(const float* __restrict__ conv_b) {
    __shared__ float L[256];
    int n = blockIdx.x, t = threadIdx.x;
    L[t] = g_lnorm[n * 256 + t];
    float b = conv_b[t];
    float xv[16];
#pragma unroll
    for (int k = 0; k < 16; k++) {
        size_t idx = (size_t)(n * 16 + k) * COUT + t;
        xv[k] = fmaxf(g_xpart[0][idx] + g_xpart[1][idx] + b, 0.f);
    }
    __syncthreads();
#pragma unroll
    for (int i = 0; i < 16; i++) {
        float y = 0.f;
#pragma unroll
        for (int j = 0; j < 16; j++) y += L[i * 16 + j] * xv[j];
        g_y[(size_t)n * KFC + i * 256 + t] = y;
    }
}

// ---------------- K5: FC GEMM (unchanged) ----------------
__global__ void k5_fc(const float* __restrict__ fc_w) {
    __shared__ float As[2][64][16];
    __shared__ float Bs[2][128][17];
    int tid = threadIdx.x;
    int b = blockIdx.x;
    int ks = b & 15;
    int dt = (b >> 4) & 3;
    int nh = b >> 6;
    int n0 = nh * 64, d0 = dt * 128, k0 = ks * 256;
    int warp = tid >> 5, lane = tid & 31;
    int nr0 = warp * 8;

    auto load_tile = [&](int t, int buf) {
        int kbase = k0 + t * 16;
#pragma unroll
        for (int i = 0; i < 4; i++) {
            int e = tid + 256 * i;
            int nn = e >> 4, kk = e & 15;
            cp4(&As[buf][nn][kk], &g_y[(size_t)(n0 + nn) * KFC + kbase + kk]);
        }
#pragma unroll
        for (int i = 0; i < 8; i++) {
            int e = tid + 256 * i;
            int dd = e >> 4, kk = e & 15;
            cp4(&Bs[buf][dd][kk], &fc_w[(size_t)(d0 + dd) * KFC + kbase + kk]);
        }
    };

    float acc[8][4];
#pragma unroll
    for (int i = 0; i < 8; i++)
#pragma unroll
        for (int j = 0; j < 4; j++) acc[i][j] = 0.f;

    load_tile(0, 0);
    cp_commit();

    for (int t = 0; t < 16; t++) {
        int buf = t & 1;
        if (t + 1 < 16) {
            load_tile(t + 1, 1 - buf);
            cp_commit();
            cp_wait<1>();
        } else {
            cp_wait<0>();
        }
        __syncthreads();

#pragma unroll
        for (int kk = 0; kk < 16; kk++) {
            float av[8];
#pragma unroll
            for (int i = 0; i < 8; i++) av[i] = As[buf][nr0 + i][kk];
            float bv[4];
#pragma unroll
            for (int j = 0; j < 4; j++) bv[j] = Bs[buf][lane + 32 * j][kk];
#pragma unroll
            for (int i = 0; i < 8; i++)
#pragma unroll
                for (int j = 0; j < 4; j++) acc[i][j] += av[i] * bv[j];
        }
        __syncthreads();
    }

#pragma unroll
    for (int i = 0; i < 8; i++)
#pragma unroll
        for (int j = 0; j < 4; j++)
            g_partial[(size_t)ks * (NBATCH * DOUT) + (n0 + nr0 + i) * DOUT + d0 +
                      lane + 32 * j] = acc[i][j];
}

// ---------------- K6: reduce k-splits + bias ----------------
__global__ void k6_reduce(const float* __restrict__ fc_b, float* __restrict__ out) {
    int idx = blockIdx.x * 256 + threadIdx.x;
    int d = idx & (DOUT - 1);
    float s = fc_b[d];
#pragma unroll
    for (int ks = 0; ks < 16; ks++) s += g_partial[(size_t)ks * (NBATCH * DOUT) + idx];
    out[idx] = s;
}

// ---------------- launch ----------------
extern "C" void kernel_launch(void* const* d_in, const int* in_sizes, int n_in,
                              void* d_out, int out_size) {
    const float* sounds = (const float*)d_in[0];
    const float* conv_w = (const float*)d_in[1];
    const float* conv_b = (const float*)d_in[2];
    const float* fc_w   = (const float*)d_in[3];
    const float* fc_b   = (const float*)d_in[4];
    float* out = (float*)d_out;

    cudaFuncSetAttribute(k3_gemm1, cudaFuncAttributeMaxDynamicSharedMemorySize, SMEMSZ);

    k0_prep<<<512, 256>>>(conv_w);
    k1_sum<<<dim3(128, 4), 256>>>(sounds);
    k2_topk<<<128, 256>>>();
    k3_gemm1<<<dim3(64, 2), 256, SMEMSZ>>>(sounds);
    k3b_mix<<<128, 256>>>(conv_b);
    k5_fc<<<128, 256>>>(fc_w);
    k6_reduce<<<256, 256>>>(fc_b, out);
}

// round 5
// speedup vs baseline: 1.8581x; 1.0134x over previous
#include <cuda_runtime.h>
#include <cuda_bf16.h>
#include <cstdint>
#include <math.h>

#define NBATCH 128
#define CIN    2048
#define COUT   256
#define KNODES 16
#define SPOS   256
#define DOUT   512
#define KFC    4096
#define MROWS  2048   // NBATCH * KNODES

// ---------------- device scratch ----------------
__device__ float g_part[NBATCH * 4 * SPOS];
__device__ int   g_pos[NBATCH * KNODES];
__device__ float g_lnorm[NBATCH * KNODES * KNODES];
__device__ float g_y[NBATCH * KNODES * COUT];
__device__ float g_partial[16 * NBATCH * DOUT];
__device__ __nv_bfloat16 g_whi[COUT * CIN];      // conv_w hi plane
__device__ __nv_bfloat16 g_wlo[COUT * CIN];      // conv_w lo plane
__device__ __nv_bfloat16 g_ahi[MROWS * CIN];     // gathered nodes hi plane
__device__ __nv_bfloat16 g_alo[MROWS * CIN];     // gathered nodes lo plane
__device__ float g_xpart[2][MROWS * COUT];       // k-split conv partials

// ---------------- async copy helpers ----------------
__device__ __forceinline__ void cp4(void* smem, const void* gmem) {
    unsigned int s = (unsigned int)__cvta_generic_to_shared(smem);
    asm volatile("cp.async.ca.shared.global [%0], [%1], 4;\n" :: "r"(s), "l"(gmem));
}
__device__ __forceinline__ void cp16(void* smem, const void* gmem) {
    unsigned int s = (unsigned int)__cvta_generic_to_shared(smem);
    asm volatile("cp.async.cg.shared.global [%0], [%1], 16;\n" :: "r"(s), "l"(gmem));
}
__device__ __forceinline__ void cp_commit() {
    asm volatile("cp.async.commit_group;\n" ::: "memory");
}
template <int N>
__device__ __forceinline__ void cp_wait() {
    asm volatile("cp.async.wait_group %0;\n" :: "n"(N) : "memory");
}

// ---------------- mma helpers ----------------
__device__ __forceinline__ void mma_bf16(float* c, const unsigned* a, const unsigned* b) {
    asm volatile(
        "mma.sync.aligned.m16n8k16.row.col.f32.bf16.bf16.f32 "
        "{%0,%1,%2,%3},{%4,%5,%6,%7},{%8,%9},{%0,%1,%2,%3};\n"
        : "+f"(c[0]), "+f"(c[1]), "+f"(c[2]), "+f"(c[3])
        : "r"(a[0]), "r"(a[1]), "r"(a[2]), "r"(a[3]), "r"(b[0]), "r"(b[1]));
}
__device__ __forceinline__ void ldsm_x4(unsigned* r, const void* p) {
    unsigned a = (unsigned)__cvta_generic_to_shared(p);
    asm volatile("ldmatrix.sync.aligned.m8n8.x4.shared.b16 {%0,%1,%2,%3}, [%4];\n"
                 : "=r"(r[0]), "=r"(r[1]), "=r"(r[2]), "=r"(r[3]) : "r"(a));
}

// ---------------- K0: split conv_w into bf16 hi/lo planes ----------------
__global__ void k0_prep(const float* __restrict__ conv_w) {
    int i = (blockIdx.x * 256 + threadIdx.x) * 4;
#pragma unroll
    for (int j = 0; j < 4; j++) {
        float w = conv_w[i + j];
        __nv_bfloat16 h = __float2bfloat16_rn(w);
        g_whi[i + j] = h;
        g_wlo[i + j] = __float2bfloat16_rn(w - __bfloat162float(h));
    }
}

// ---------------- K1: channel sum ----------------
__global__ void k1_sum(const float* __restrict__ s) {
    int n = blockIdx.x, g = blockIdx.y, pos = threadIdx.x;
    const float* base = s + ((size_t)n * CIN + (size_t)g * 512) * SPOS + pos;
    float a[8];
#pragma unroll
    for (int i = 0; i < 8; i++) a[i] = 0.f;
#pragma unroll 2
    for (int c = 0; c < 512; c += 8) {
#pragma unroll
        for (int i = 0; i < 8; i++) a[i] += base[(c + i) * SPOS];
    }
    float r = ((a[0] + a[1]) + (a[2] + a[3])) + ((a[4] + a[5]) + (a[6] + a[7]));
    g_part[(n * 4 + g) * SPOS + pos] = r;
}

// ---------------- K2: top-k + lnorm ----------------
__global__ void k2_topk(void) {
    __shared__ float feat[SPOS];
    __shared__ float rval[SPOS];
    __shared__ int   ridx[SPOS];
    __shared__ int   sel[KNODES];
    __shared__ int   rr[KNODES], cc[KNODES];
    __shared__ float Amat[KNODES][KNODES];
    __shared__ float dinv[KNODES];

    int n = blockIdx.x, t = threadIdx.x;
    float f = g_part[(n * 4 + 0) * SPOS + t] + g_part[(n * 4 + 1) * SPOS + t] +
              g_part[(n * 4 + 2) * SPOS + t] + g_part[(n * 4 + 3) * SPOS + t];
    feat[t] = f;
    __syncthreads();

    for (int it = 0; it < KNODES; it++) {
        rval[t] = feat[t];
        ridx[t] = t;
        __syncthreads();
        for (int sstep = 128; sstep > 0; sstep >>= 1) {
            if (t < sstep) {
                float v2 = rval[t + sstep];
                int   i2 = ridx[t + sstep];
                if (v2 > rval[t] || (v2 == rval[t] && i2 < ridx[t])) {
                    rval[t] = v2;
                    ridx[t] = i2;
                }
            }
            __syncthreads();
        }
        if (t == 0) {
            sel[it] = ridx[0];
            feat[ridx[0]] = -3.4e38f;
        }
        __syncthreads();
    }

    if (t < KNODES) {
        int p = sel[t];
        int r = (p < 16) ? 0 : ((p >> 4) - 1);
        int q = p & 15;
        int c = (q == 0) ? 15 : (q - 1);
        rr[t] = r;
        cc[t] = c;
        g_pos[n * KNODES + t] = r * 16 + c;
    }
    __syncthreads();
    {
        int i = t >> 4, j = t & 15;
        float dr = (float)(rr[i] - rr[j]);
        float dc = (float)(cc[i] - cc[j]);
        Amat[i][j] = expf(-(dr * dr + dc * dc) / (2.0f * (float)KNODES));
    }
    __syncthreads();
    if (t < KNODES) {
        float s = 0.f;
#pragma unroll
        for (int j = 0; j < KNODES; j++) s += Amat[t][j];
        dinv[t] = 1.0f / sqrtf(s);
    }
    __syncthreads();
    {
        int i = t >> 4, j = t & 15;
        g_lnorm[n * 256 + t] = Amat[i][j] * dinv[i] * dinv[j];
    }
}

// ---------------- K2b: gather nodes + split to bf16 hi/lo planes ----------------
// grid (128 n, 8 cslice), block 256 = (16 k, 16 ci).
// Read: warp holds all 16 node-positions of one (n,c) plane -> sector dedupe.
// Write: smem transpose -> warp-coalesced bf16x2 rows.
__global__ void k2b_gather(const float* __restrict__ sounds) {
    __shared__ __nv_bfloat162 smh[16][17];
    __shared__ __nv_bfloat162 sml[16][17];
    const int n = blockIdx.x, slice = blockIdx.y;
    const int tid = threadIdx.x;
    const int k = tid & 15, ci = tid >> 4;   // reader role
    const int k2 = tid >> 4, c2 = tid & 15;  // writer role
    const int pos = g_pos[n * KNODES + k];
    const float* base = sounds + ((size_t)n * CIN) * SPOS + pos;
    const int c0s = slice * 256;

    float v0, v1;
    {
        int c = c0s + ci * 2;
        v0 = __ldg(&base[(size_t)c * SPOS]);
        v1 = __ldg(&base[(size_t)(c + 1) * SPOS]);
    }
#pragma unroll
    for (int ch = 0; ch < 8; ch++) {
        float u0 = v0, u1 = v1;
        if (ch + 1 < 8) {   // prefetch next pass
            int c = c0s + (ch + 1) * 32 + ci * 2;
            v0 = __ldg(&base[(size_t)c * SPOS]);
            v1 = __ldg(&base[(size_t)(c + 1) * SPOS]);
        }
        __nv_bfloat16 h0 = __float2bfloat16_rn(u0);
        __nv_bfloat16 h1 = __float2bfloat16_rn(u1);
        __nv_bfloat16 l0 = __float2bfloat16_rn(u0 - __bfloat162float(h0));
        __nv_bfloat16 l1 = __float2bfloat16_rn(u1 - __bfloat162float(h1));
        __syncthreads();
        smh[ci][k] = __nv_bfloat162(h0, h1);
        sml[ci][k] = __nv_bfloat162(l0, l1);
        __syncthreads();
        size_t o = (size_t)(n * 16 + k2) * (CIN / 2) + (c0s + ch * 32) / 2 + c2;
        ((__nv_bfloat162*)g_ahi)[o] = smh[c2][k2];
        ((__nv_bfloat162*)g_alo)[o] = sml[c2][k2];
    }
}

// ---------------- K3g: split-bf16 tensor-core GEMM on compact planes ----------------
// D[row, o] = nodes[row,:] . conv_w[o,:]  (3-term bf16 split)
// grid (32 mt, 4 = nt*2 + ks... -> y: nt = y&1, ks = y>>1), 256 threads.
// Block tile M=64, N=128, K-chunk 1024, k-tile 32, double-buffered cp.async.
#define KT     32
#define KITERS 32
#define APITCH 40
#define BPITCH 40
#define SMB_OFF 0
#define SMA_OFF (2 * 2 * 128 * BPITCH * 2)        // 40960
#define SMEMSZ  (SMA_OFF + 2 * 2 * 64 * APITCH * 2)  // 61440

__global__ void __launch_bounds__(256, 2)
k3g_gemm(void) {
    extern __shared__ __align__(16) char smraw[];
    __nv_bfloat16* Bsm = (__nv_bfloat16*)(smraw + SMB_OFF);
    __nv_bfloat16* Asm = (__nv_bfloat16*)(smraw + SMA_OFF);

    const int tid = threadIdx.x;
    const int mt  = blockIdx.x;          // 0..31
    const int nt  = blockIdx.y & 1;      // 0..1
    const int ks  = blockIdx.y >> 1;     // 0..1
    const int m0  = mt * 64;
    const int ncol0 = nt * 128;
    const int kc0 = ks * 1024;

    auto load_tile = [&](int t, int buf) {
        const int k0 = kc0 + t * KT;
        // A: 64 rows x 32 k x 2 planes
        {
            int row = tid >> 2, kq = (tid & 3) * 8;
            cp16(&Asm[((buf * 2 + 0) * 64 + row) * APITCH + kq],
                 &g_ahi[(size_t)(m0 + row) * CIN + k0 + kq]);
            cp16(&Asm[((buf * 2 + 1) * 64 + row) * APITCH + kq],
                 &g_alo[(size_t)(m0 + row) * CIN + k0 + kq]);
        }
        // B: 128 cols x 32 k x 2 planes
#pragma unroll
        for (int i = 0; i < 2; i++) {
            int q = tid + 256 * i;
            int col = q >> 2, kq = (q & 3) * 8;
            cp16(&Bsm[((buf * 2 + 0) * 128 + col) * BPITCH + kq],
                 &g_whi[(size_t)(ncol0 + col) * CIN + k0 + kq]);
            cp16(&Bsm[((buf * 2 + 1) * 128 + col) * BPITCH + kq],
                 &g_wlo[(size_t)(ncol0 + col) * CIN + k0 + kq]);
        }
    };

    const int warp = tid >> 5, lane = tid & 31;
    const int wm = warp & 1, wn = warp >> 1;   // 2 x 4 warp grid
    const int mrow0 = wm * 32;
    const int ncb = wn * 32;
    const int aRow = lane & 15, aCol = (lane >> 4) * 8;
    const int bRow = (lane & 7) + ((lane >> 4) & 1) * 8;
    const int bCol = ((lane >> 3) & 1) * 8;

    float acc[2][4][4];
#pragma unroll
    for (int mi = 0; mi < 2; mi++)
#pragma unroll
        for (int nj = 0; nj < 4; nj++)
#pragma unroll
            for (int v = 0; v < 4; v++) acc[mi][nj][v] = 0.f;

    load_tile(0, 0);
    cp_commit();

    for (int t = 0; t < KITERS; t++) {
        const int buf = t & 1;
        cp_wait<0>();
        __syncthreads();
        if (t + 1 < KITERS) {
            load_tile(t + 1, 1 - buf);
            cp_commit();
        }
        const __nv_bfloat16* Ah = Asm + (buf * 2 + 0) * 64 * APITCH;
        const __nv_bfloat16* Al = Asm + (buf * 2 + 1) * 64 * APITCH;
        const __nv_bfloat16* Bh = Bsm + (buf * 2 + 0) * 128 * BPITCH;
        const __nv_bfloat16* Bl = Bsm + (buf * 2 + 1) * 128 * BPITCH;
#pragma unroll
        for (int s16 = 0; s16 < KT; s16 += 16) {
            unsigned ah[2][4], al[2][4], bh[2][4], bl[2][4];
            ldsm_x4(ah[0], &Ah[(mrow0 + aRow) * APITCH + s16 + aCol]);
            ldsm_x4(ah[1], &Ah[(mrow0 + 16 + aRow) * APITCH + s16 + aCol]);
            ldsm_x4(al[0], &Al[(mrow0 + aRow) * APITCH + s16 + aCol]);
            ldsm_x4(al[1], &Al[(mrow0 + 16 + aRow) * APITCH + s16 + aCol]);
            ldsm_x4(bh[0], &Bh[(ncb + bRow) * BPITCH + s16 + bCol]);
            ldsm_x4(bh[1], &Bh[(ncb + 16 + bRow) * BPITCH + s16 + bCol]);
            ldsm_x4(bl[0], &Bl[(ncb + bRow) * BPITCH + s16 + bCol]);
            ldsm_x4(bl[1], &Bl[(ncb + 16 + bRow) * BPITCH + s16 + bCol]);
#pragma unroll
            for (int mi = 0; mi < 2; mi++) {
#pragma unroll
                for (int nj = 0; nj < 4; nj++) {
                    const unsigned* bhf = &bh[nj >> 1][(nj & 1) * 2];
                    const unsigned* blf = &bl[nj >> 1][(nj & 1) * 2];
                    mma_bf16(acc[mi][nj], ah[mi], bhf);
                    mma_bf16(acc[mi][nj], ah[mi], blf);
                    mma_bf16(acc[mi][nj], al[mi], bhf);
                }
            }
        }
    }

    // write fp32 partials
    {
        int r = lane >> 2, cq = (lane & 3) * 2;
        float* dst = g_xpart[ks];
#pragma unroll
        for (int mi = 0; mi < 2; mi++) {
#pragma unroll
            for (int nj = 0; nj < 4; nj++) {
                int row0 = m0 + mrow0 + mi * 16 + r;
                int col = ncol0 + ncb + nj * 8 + cq;
                *(float2*)&dst[(size_t)row0 * COUT + col] =
                    make_float2(acc[mi][nj][0], acc[mi][nj][1]);
                *(float2*)&dst[(size_t)(row0 + 8) * COUT + col] =
                    make_float2(acc[mi][nj][2], acc[mi][nj][3]);
            }
        }
    }
}

// ---------------- K3b: sum splits + bias + relu + lnorm mix ----------------
__global__ void k3b_mix(const float* __restrict__ conv_b) {
    __shared__ float L[256];
    int n = blockIdx.x, t = threadIdx.x;
    L[t] = g_lnorm[n * 256 + t];
    float b = conv_b[t];
    float xv[16];
#pragma unroll
    for (int k = 0; k < 16; k++) {
        size_t idx = (size_t)(n * 16 + k) * COUT + t;
        xv[k] = fmaxf(g_xpart[0][idx] + g_xpart[1][idx] + b, 0.f);
    }
    __syncthreads();
#pragma unroll
    for (int i = 0; i < 16; i++) {
        float y = 0.f;
#pragma unroll
        for (int j = 0; j < 16; j++) y += L[i * 16 + j] * xv[j];
        g_y[(size_t)n * KFC + i * 256 + t] = y;
    }
}

// ---------------- K5: FC GEMM (fp32, k-split x16) ----------------
__global__ void k5_fc(const float* __restrict__ fc_w) {
    __shared__ float As[2][64][16];
    __shared__ float Bs[2][128][17];
    int tid = threadIdx.x;
    int b = blockIdx.x;
    int ks = b & 15;
    int dt = (b >> 4) & 3;
    int nh = b >> 6;
    int n0 = nh * 64, d0 = dt * 128, k0 = ks * 256;
    int warp = tid >> 5, lane = tid & 31;
    int nr0 = warp * 8;

    auto load_tile = [&](int t, int buf) {
        int kbase = k0 + t * 16;
#pragma unroll
        for (int i = 0; i < 4; i++) {
            int e = tid + 256 * i;
            int nn = e >> 4, kk = e & 15;
            cp4(&As[buf][nn][kk], &g_y[(size_t)(n0 + nn) * KFC + kbase + kk]);
        }
#pragma unroll
        for (int i = 0; i < 8; i++) {
            int e = tid + 256 * i;
            int dd = e >> 4, kk = e & 15;
            cp4(&Bs[buf][dd][kk], &fc_w[(size_t)(d0 + dd) * KFC + kbase + kk]);
        }
    };

    float acc[8][4];
#pragma unroll
    for (int i = 0; i < 8; i++)
#pragma unroll
        for (int j = 0; j < 4; j++) acc[i][j] = 0.f;

    load_tile(0, 0);
    cp_commit();

    for (int t = 0; t < 16; t++) {
        int buf = t & 1;
        if (t + 1 < 16) {
            load_tile(t + 1, 1 - buf);
            cp_commit();
            cp_wait<1>();
        } else {
            cp_wait<0>();
        }
        __syncthreads();

#pragma unroll
        for (int kk = 0; kk < 16; kk++) {
            float av[8];
#pragma unroll
            for (int i = 0; i < 8; i++) av[i] = As[buf][nr0 + i][kk];
            float bv[4];
#pragma unroll
            for (int j = 0; j < 4; j++) bv[j] = Bs[buf][lane + 32 * j][kk];
#pragma unroll
            for (int i = 0; i < 8; i++)
#pragma unroll
                for (int j = 0; j < 4; j++) acc[i][j] += av[i] * bv[j];
        }
        __syncthreads();
    }

#pragma unroll
    for (int i = 0; i < 8; i++)
#pragma unroll
        for (int j = 0; j < 4; j++)
            g_partial[(size_t)ks * (NBATCH * DOUT) + (n0 + nr0 + i) * DOUT + d0 +
                      lane + 32 * j] = acc[i][j];
}

// ---------------- K6: reduce k-splits + bias ----------------
__global__ void k6_reduce(const float* __restrict__ fc_b, float* __restrict__ out) {
    int idx = blockIdx.x * 256 + threadIdx.x;
    int d = idx & (DOUT - 1);
    float s = fc_b[d];
#pragma unroll
    for (int ks = 0; ks < 16; ks++) s += g_partial[(size_t)ks * (NBATCH * DOUT) + idx];
    out[idx] = s;
}

// ---------------- launch ----------------
extern "C" void kernel_launch(void* const* d_in, const int* in_sizes, int n_in,
                              void* d_out, int out_size) {
    const float* sounds = (const float*)d_in[0];
    const float* conv_w = (const float*)d_in[1];
    const float* conv_b = (const float*)d_in[2];
    const float* fc_w   = (const float*)d_in[3];
    const float* fc_b   = (const float*)d_in[4];
    float* out = (float*)d_out;

    cudaFuncSetAttribute(k3g_gemm, cudaFuncAttributeMaxDynamicSharedMemorySize, SMEMSZ);

    k0_prep<<<512, 256>>>(conv_w);
    k1_sum<<<dim3(128, 4), 256>>>(sounds);
    k2_topk<<<128, 256>>>();
    k2b_gather<<<dim3(128, 8), 256>>>(sounds);
    k3g_gemm<<<dim3(32, 4), 256, SMEMSZ>>>();
    k3b_mix<<<128, 256>>>(conv_b);
    k5_fc<<<128, 256>>>(fc_w);
    k6_reduce<<<256, 256>>>(fc_b, out);
}

// round 6
// speedup vs baseline: 1.9270x; 1.0371x over previous
#include <cuda_runtime.h>
#include <cuda_bf16.h>
#include <cstdint>
#include <math.h>

#define NBATCH 128
#define CIN    2048
#define COUT   256
#define KNODES 16
#define SPOS   256
#define DOUT   512
#define KFC    4096
#define MROWS  2048   // NBATCH * KNODES
#define KSPLIT 4

// ---------------- device scratch ----------------
__device__ float g_part[NBATCH * 4 * SPOS];
__device__ int   g_pos[NBATCH * KNODES];
__device__ float g_lnorm[NBATCH * KNODES * KNODES];
__device__ float g_y[NBATCH * KNODES * COUT];
__device__ float g_partial[16 * NBATCH * DOUT];
__device__ __nv_bfloat16 g_whi[COUT * CIN];
__device__ __nv_bfloat16 g_wlo[COUT * CIN];
__device__ __nv_bfloat16 g_ahi[MROWS * CIN];
__device__ __nv_bfloat16 g_alo[MROWS * CIN];
__device__ float g_xpart[KSPLIT][MROWS * COUT];

// ---------------- async copy helpers ----------------
__device__ __forceinline__ void cp4(void* smem, const void* gmem) {
    unsigned int s = (unsigned int)__cvta_generic_to_shared(smem);
    asm volatile("cp.async.ca.shared.global [%0], [%1], 4;\n" :: "r"(s), "l"(gmem));
}
__device__ __forceinline__ void cp16(void* smem, const void* gmem) {
    unsigned int s = (unsigned int)__cvta_generic_to_shared(smem);
    asm volatile("cp.async.cg.shared.global [%0], [%1], 16;\n" :: "r"(s), "l"(gmem));
}
__device__ __forceinline__ void cp_commit() {
    asm volatile("cp.async.commit_group;\n" ::: "memory");
}
template <int N>
__device__ __forceinline__ void cp_wait() {
    asm volatile("cp.async.wait_group %0;\n" :: "n"(N) : "memory");
}

// ---------------- mma helpers ----------------
__device__ __forceinline__ void mma_bf16(float* c, const unsigned* a, const unsigned* b) {
    asm volatile(
        "mma.sync.aligned.m16n8k16.row.col.f32.bf16.bf16.f32 "
        "{%0,%1,%2,%3},{%4,%5,%6,%7},{%8,%9},{%0,%1,%2,%3};\n"
        : "+f"(c[0]), "+f"(c[1]), "+f"(c[2]), "+f"(c[3])
        : "r"(a[0]), "r"(a[1]), "r"(a[2]), "r"(a[3]), "r"(b[0]), "r"(b[1]));
}
__device__ __forceinline__ void ldsm_x4(unsigned* r, const void* p) {
    unsigned a = (unsigned)__cvta_generic_to_shared(p);
    asm volatile("ldmatrix.sync.aligned.m8n8.x4.shared.b16 {%0,%1,%2,%3}, [%4];\n"
                 : "=r"(r[0]), "=r"(r[1]), "=r"(r[2]), "=r"(r[3]) : "r"(a));
}

// ---------------- K0: split conv_w into bf16 hi/lo planes ----------------
__global__ void k0_prep(const float* __restrict__ conv_w) {
    int i = (blockIdx.x * 256 + threadIdx.x) * 4;
#pragma unroll
    for (int j = 0; j < 4; j++) {
        float w = conv_w[i + j];
        __nv_bfloat16 h = __float2bfloat16_rn(w);
        g_whi[i + j] = h;
        g_wlo[i + j] = __float2bfloat16_rn(w - __bfloat162float(h));
    }
}

// ---------------- K1: channel sum ----------------
__global__ void k1_sum(const float* __restrict__ s) {
    int n = blockIdx.x, g = blockIdx.y, pos = threadIdx.x;
    const float* base = s + ((size_t)n * CIN + (size_t)g * 512) * SPOS + pos;
    float a[8];
#pragma unroll
    for (int i = 0; i < 8; i++) a[i] = 0.f;
#pragma unroll 2
    for (int c = 0; c < 512; c += 8) {
#pragma unroll
        for (int i = 0; i < 8; i++) a[i] += base[(c + i) * SPOS];
    }
    float r = ((a[0] + a[1]) + (a[2] + a[3])) + ((a[4] + a[5]) + (a[6] + a[7]));
    g_part[(n * 4 + g) * SPOS + pos] = r;
}

// ---------------- K2: top-k + lnorm ----------------
__global__ void k2_topk(void) {
    __shared__ float feat[SPOS];
    __shared__ float rval[SPOS];
    __shared__ int   ridx[SPOS];
    __shared__ int   sel[KNODES];
    __shared__ int   rr[KNODES], cc[KNODES];
    __shared__ float Amat[KNODES][KNODES];
    __shared__ float dinv[KNODES];

    int n = blockIdx.x, t = threadIdx.x;
    float f = g_part[(n * 4 + 0) * SPOS + t] + g_part[(n * 4 + 1) * SPOS + t] +
              g_part[(n * 4 + 2) * SPOS + t] + g_part[(n * 4 + 3) * SPOS + t];
    feat[t] = f;
    __syncthreads();

    for (int it = 0; it < KNODES; it++) {
        rval[t] = feat[t];
        ridx[t] = t;
        __syncthreads();
        for (int sstep = 128; sstep > 0; sstep >>= 1) {
            if (t < sstep) {
                float v2 = rval[t + sstep];
                int   i2 = ridx[t + sstep];
                if (v2 > rval[t] || (v2 == rval[t] && i2 < ridx[t])) {
                    rval[t] = v2;
                    ridx[t] = i2;
                }
            }
            __syncthreads();
        }
        if (t == 0) {
            sel[it] = ridx[0];
            feat[ridx[0]] = -3.4e38f;
        }
        __syncthreads();
    }

    if (t < KNODES) {
        int p = sel[t];
        int r = (p < 16) ? 0 : ((p >> 4) - 1);
        int q = p & 15;
        int c = (q == 0) ? 15 : (q - 1);
        rr[t] = r;
        cc[t] = c;
        g_pos[n * KNODES + t] = r * 16 + c;
    }
    __syncthreads();
    {
        int i = t >> 4, j = t & 15;
        float dr = (float)(rr[i] - rr[j]);
        float dc = (float)(cc[i] - cc[j]);
        Amat[i][j] = expf(-(dr * dr + dc * dc) / (2.0f * (float)KNODES));
    }
    __syncthreads();
    if (t < KNODES) {
        float s = 0.f;
#pragma unroll
        for (int j = 0; j < KNODES; j++) s += Amat[t][j];
        dinv[t] = 1.0f / sqrtf(s);
    }
    __syncthreads();
    {
        int i = t >> 4, j = t & 15;
        g_lnorm[n * 256 + t] = Amat[i][j] * dinv[i] * dinv[j];
    }
}

// ---------------- K2b: gather nodes + split to bf16 hi/lo planes ----------------
__global__ void k2b_gather(const float* __restrict__ sounds) {
    __shared__ __nv_bfloat162 smh[16][17];
    __shared__ __nv_bfloat162 sml[16][17];
    const int n = blockIdx.x, slice = blockIdx.y;
    const int tid = threadIdx.x;
    const int k = tid & 15, ci = tid >> 4;
    const int k2 = tid >> 4, c2 = tid & 15;
    const int pos = g_pos[n * KNODES + k];
    const float* base = sounds + ((size_t)n * CIN) * SPOS + pos;
    const int c0s = slice * 256;

    float v0, v1;
    {
        int c = c0s + ci * 2;
        v0 = __ldg(&base[(size_t)c * SPOS]);
        v1 = __ldg(&base[(size_t)(c + 1) * SPOS]);
    }
#pragma unroll
    for (int ch = 0; ch < 8; ch++) {
        float u0 = v0, u1 = v1;
        if (ch + 1 < 8) {
            int c = c0s + (ch + 1) * 32 + ci * 2;
            v0 = __ldg(&base[(size_t)c * SPOS]);
            v1 = __ldg(&base[(size_t)(c + 1) * SPOS]);
        }
        __nv_bfloat16 h0 = __float2bfloat16_rn(u0);
        __nv_bfloat16 h1 = __float2bfloat16_rn(u1);
        __nv_bfloat16 l0 = __float2bfloat16_rn(u0 - __bfloat162float(h0));
        __nv_bfloat16 l1 = __float2bfloat16_rn(u1 - __bfloat162float(h1));
        __syncthreads();
        smh[ci][k] = __nv_bfloat162(h0, h1);
        sml[ci][k] = __nv_bfloat162(l0, l1);
        __syncthreads();
        size_t o = (size_t)(n * 16 + k2) * (CIN / 2) + (c0s + ch * 32) / 2 + c2;
        ((__nv_bfloat162*)g_ahi)[o] = smh[c2][k2];
        ((__nv_bfloat162*)g_alo)[o] = sml[c2][k2];
    }
}

// ---------------- K3g: split-bf16 tensor-core GEMM on compact planes ----------------
// grid (32 mt, 8): nt = y&1, ks = y>>1 (K-split 4, chunk 512). 256 threads.
#define KT     32
#define KITERS 16           // 512 / 32
#define APITCH 40
#define BPITCH 40
#define SMB_OFF 0
#define SMA_OFF (2 * 2 * 128 * BPITCH * 2)           // 40960
#define SMEMSZ  (SMA_OFF + 2 * 2 * 64 * APITCH * 2)  // 61440

__global__ void __launch_bounds__(256, 2)
k3g_gemm(void) {
    extern __shared__ __align__(16) char smraw[];
    __nv_bfloat16* Bsm = (__nv_bfloat16*)(smraw + SMB_OFF);
    __nv_bfloat16* Asm = (__nv_bfloat16*)(smraw + SMA_OFF);

    const int tid = threadIdx.x;
    const int mt  = blockIdx.x;          // 0..31
    const int nt  = blockIdx.y & 1;      // 0..1
    const int ks  = blockIdx.y >> 1;     // 0..3
    const int m0  = mt * 64;
    const int ncol0 = nt * 128;
    const int kc0 = ks * 512;

    auto load_tile = [&](int t, int buf) {
        const int k0 = kc0 + t * KT;
        {
            int row = tid >> 2, kq = (tid & 3) * 8;
            cp16(&Asm[((buf * 2 + 0) * 64 + row) * APITCH + kq],
                 &g_ahi[(size_t)(m0 + row) * CIN + k0 + kq]);
            cp16(&Asm[((buf * 2 + 1) * 64 + row) * APITCH + kq],
                 &g_alo[(size_t)(m0 + row) * CIN + k0 + kq]);
        }
#pragma unroll
        for (int i = 0; i < 2; i++) {
            int q = tid + 256 * i;
            int col = q >> 2, kq = (q & 3) * 8;
            cp16(&Bsm[((buf * 2 + 0) * 128 + col) * BPITCH + kq],
                 &g_whi[(size_t)(ncol0 + col) * CIN + k0 + kq]);
            cp16(&Bsm[((buf * 2 + 1) * 128 + col) * BPITCH + kq],
                 &g_wlo[(size_t)(ncol0 + col) * CIN + k0 + kq]);
        }
    };

    const int warp = tid >> 5, lane = tid & 31;
    const int wm = warp & 1, wn = warp >> 1;
    const int mrow0 = wm * 32;
    const int ncb = wn * 32;
    const int aRow = lane & 15, aCol = (lane >> 4) * 8;
    const int bRow = (lane & 7) + ((lane >> 4) & 1) * 8;
    const int bCol = ((lane >> 3) & 1) * 8;

    float acc[2][4][4];
#pragma unroll
    for (int mi = 0; mi < 2; mi++)
#pragma unroll
        for (int nj = 0; nj < 4; nj++)
#pragma unroll
            for (int v = 0; v < 4; v++) acc[mi][nj][v] = 0.f;

    load_tile(0, 0);
    cp_commit();

    for (int t = 0; t < KITERS; t++) {
        const int buf = t & 1;
        cp_wait<0>();
        __syncthreads();
        if (t + 1 < KITERS) {
            load_tile(t + 1, 1 - buf);
            cp_commit();
        }
        const __nv_bfloat16* Ah = Asm + (buf * 2 + 0) * 64 * APITCH;
        const __nv_bfloat16* Al = Asm + (buf * 2 + 1) * 64 * APITCH;
        const __nv_bfloat16* Bh = Bsm + (buf * 2 + 0) * 128 * BPITCH;
        const __nv_bfloat16* Bl = Bsm + (buf * 2 + 1) * 128 * BPITCH;
#pragma unroll
        for (int s16 = 0; s16 < KT; s16 += 16) {
            unsigned ah[2][4], al[2][4], bh[2][4], bl[2][4];
            ldsm_x4(ah[0], &Ah[(mrow0 + aRow) * APITCH + s16 + aCol]);
            ldsm_x4(ah[1], &Ah[(mrow0 + 16 + aRow) * APITCH + s16 + aCol]);
            ldsm_x4(al[0], &Al[(mrow0 + aRow) * APITCH + s16 + aCol]);
            ldsm_x4(al[1], &Al[(mrow0 + 16 + aRow) * APITCH + s16 + aCol]);
            ldsm_x4(bh[0], &Bh[(ncb + bRow) * BPITCH + s16 + bCol]);
            ldsm_x4(bh[1], &Bh[(ncb + 16 + bRow) * BPITCH + s16 + bCol]);
            ldsm_x4(bl[0], &Bl[(ncb + bRow) * BPITCH + s16 + bCol]);
            ldsm_x4(bl[1], &Bl[(ncb + 16 + bRow) * BPITCH + s16 + bCol]);
#pragma unroll
            for (int mi = 0; mi < 2; mi++) {
#pragma unroll
                for (int nj = 0; nj < 4; nj++) {
                    const unsigned* bhf = &bh[nj >> 1][(nj & 1) * 2];
                    const unsigned* blf = &bl[nj >> 1][(nj & 1) * 2];
                    mma_bf16(acc[mi][nj], ah[mi], bhf);
                    mma_bf16(acc[mi][nj], ah[mi], blf);
                    mma_bf16(acc[mi][nj], al[mi], bhf);
                }
            }
        }
    }

    {
        int r = lane >> 2, cq = (lane & 3) * 2;
        float* dst = g_xpart[ks];
#pragma unroll
        for (int mi = 0; mi < 2; mi++) {
#pragma unroll
            for (int nj = 0; nj < 4; nj++) {
                int row0 = m0 + mrow0 + mi * 16 + r;
                int col = ncol0 + ncb + nj * 8 + cq;
                *(float2*)&dst[(size_t)row0 * COUT + col] =
                    make_float2(acc[mi][nj][0], acc[mi][nj][1]);
                *(float2*)&dst[(size_t)(row0 + 8) * COUT + col] =
                    make_float2(acc[mi][nj][2], acc[mi][nj][3]);
            }
        }
    }
}

// ---------------- K3b: sum splits + bias + relu + lnorm mix ----------------
__global__ void k3b_mix(const float* __restrict__ conv_b) {
    __shared__ float L[256];
    int n = blockIdx.x, t = threadIdx.x;
    L[t] = g_lnorm[n * 256 + t];
    float b = conv_b[t];
    float xv[16];
#pragma unroll
    for (int k = 0; k < 16; k++) {
        size_t idx = (size_t)(n * 16 + k) * COUT + t;
        float s = g_xpart[0][idx] + g_xpart[1][idx] + g_xpart[2][idx] +
                  g_xpart[3][idx] + b;
        xv[k] = fmaxf(s, 0.f);
    }
    __syncthreads();
#pragma unroll
    for (int i = 0; i < 16; i++) {
        float y = 0.f;
#pragma unroll
        for (int j = 0; j < 16; j++) y += L[i * 16 + j] * xv[j];
        g_y[(size_t)n * KFC + i * 256 + t] = y;
    }
}

// ---------------- K5: FC GEMM (fp32, k-split x16, 256 blocks) ----------------
// Block tile 64n x 64d over k-chunk 256, k-tile 16, double-buffered.
// grid 256 = (16 ks) x (8 dt) x (2 nh), 256 threads, thread tile 8x2.
__global__ void k5_fc(const float* __restrict__ fc_w) {
    __shared__ float As[2][64][17];
    __shared__ float Bs[2][64][17];
    int tid = threadIdx.x;
    int b = blockIdx.x;
    int ks = b & 15;
    int dt = (b >> 4) & 7;
    int nh = b >> 7;
    int n0 = nh * 64, d0 = dt * 64, k0 = ks * 256;
    int warp = tid >> 5, lane = tid & 31;
    int nr0 = warp * 8;

    auto load_tile = [&](int t, int buf) {
        int kbase = k0 + t * 16;
#pragma unroll
        for (int i = 0; i < 4; i++) {   // A: 64x16
            int e = tid + 256 * i;
            int nn = e >> 4, kk = e & 15;
            cp4(&As[buf][nn][kk], &g_y[(size_t)(n0 + nn) * KFC + kbase + kk]);
        }
#pragma unroll
        for (int i = 0; i < 4; i++) {   // B: 64x16
            int e = tid + 256 * i;
            int dd = e >> 4, kk = e & 15;
            cp4(&Bs[buf][dd][kk], &fc_w[(size_t)(d0 + dd) * KFC + kbase + kk]);
        }
    };

    float acc[8][2];
#pragma unroll
    for (int i = 0; i < 8; i++) {
        acc[i][0] = 0.f;
        acc[i][1] = 0.f;
    }

    load_tile(0, 0);
    cp_commit();

    for (int t = 0; t < 16; t++) {
        int buf = t & 1;
        if (t + 1 < 16) {
            load_tile(t + 1, 1 - buf);
            cp_commit();
            cp_wait<1>();
        } else {
            cp_wait<0>();
        }
        __syncthreads();

#pragma unroll
        for (int kk = 0; kk < 16; kk++) {
            float av[8];
#pragma unroll
            for (int i = 0; i < 8; i++) av[i] = As[buf][nr0 + i][kk];
            float b0 = Bs[buf][lane][kk];
            float b1 = Bs[buf][lane + 32][kk];
#pragma unroll
            for (int i = 0; i < 8; i++) {
                acc[i][0] += av[i] * b0;
                acc[i][1] += av[i] * b1;
            }
        }
        __syncthreads();
    }

#pragma unroll
    for (int i = 0; i < 8; i++) {
        size_t base = (size_t)ks * (NBATCH * DOUT) + (size_t)(n0 + nr0 + i) * DOUT + d0;
        g_partial[base + lane] = acc[i][0];
        g_partial[base + lane + 32] = acc[i][1];
    }
}

// ---------------- K6: reduce k-splits + bias ----------------
__global__ void k6_reduce(const float* __restrict__ fc_b, float* __restrict__ out) {
    int idx = blockIdx.x * 256 + threadIdx.x;
    int d = idx & (DOUT - 1);
    float s = fc_b[d];
#pragma unroll
    for (int ks = 0; ks < 16; ks++) s += g_partial[(size_t)ks * (NBATCH * DOUT) + idx];
    out[idx] = s;
}

// ---------------- launch ----------------
extern "C" void kernel_launch(void* const* d_in, const int* in_sizes, int n_in,
                              void* d_out, int out_size) {
    const float* sounds = (const float*)d_in[0];
    const float* conv_w = (const float*)d_in[1];
    const float* conv_b = (const float*)d_in[2];
    const float* fc_w   = (const float*)d_in[3];
    const float* fc_b   = (const float*)d_in[4];
    float* out = (float*)d_out;

    cudaFuncSetAttribute(k3g_gemm, cudaFuncAttributeMaxDynamicSharedMemorySize, SMEMSZ);

    k0_prep<<<512, 256>>>(conv_w);
    k1_sum<<<dim3(128, 4), 256>>>(sounds);
    k2_topk<<<128, 256>>>();
    k2b_gather<<<dim3(128, 8), 256>>>(sounds);
    k3g_gemm<<<dim3(32, 8), 256, SMEMSZ>>>();
    k3b_mix<<<128, 256>>>(conv_b);
    k5_fc<<<256, 256>>>(fc_w);
    k6_reduce<<<256, 256>>>(fc_b, out);
}

// round 7
// speedup vs baseline: 1.9768x; 1.0258x over previous
#include <cuda_runtime.h>
#include <cuda_bf16.h>
#include <cstdint>
#include <math.h>

#define NBATCH 128
#define CIN    2048
#define COUT   256
#define KNODES 16
#define SPOS   256
#define DOUT   512
#define KFC    4096
#define MROWS  2048   // NBATCH * KNODES
#define KSPLIT 4

// ---------------- device scratch ----------------
__device__ float g_lnorm[NBATCH * KNODES * KNODES];
__device__ float g_y[NBATCH * KNODES * COUT];
__device__ float g_partial[16 * NBATCH * DOUT];
__device__ __nv_bfloat16 g_whi[COUT * CIN];
__device__ __nv_bfloat16 g_wlo[COUT * CIN];
__device__ __nv_bfloat16 g_ahi[MROWS * CIN];
__device__ __nv_bfloat16 g_alo[MROWS * CIN];
__device__ float g_xpart[KSPLIT][MROWS * COUT];

// ---------------- async copy helpers ----------------
__device__ __forceinline__ void cp4(void* smem, const void* gmem) {
    unsigned int s = (unsigned int)__cvta_generic_to_shared(smem);
    asm volatile("cp.async.ca.shared.global [%0], [%1], 4;\n" :: "r"(s), "l"(gmem));
}
__device__ __forceinline__ void cp16(void* smem, const void* gmem) {
    unsigned int s = (unsigned int)__cvta_generic_to_shared(smem);
    asm volatile("cp.async.cg.shared.global [%0], [%1], 16;\n" :: "r"(s), "l"(gmem));
}
__device__ __forceinline__ void cp_commit() {
    asm volatile("cp.async.commit_group;\n" ::: "memory");
}
template <int N>
__device__ __forceinline__ void cp_wait() {
    asm volatile("cp.async.wait_group %0;\n" :: "n"(N) : "memory");
}

// ---------------- mma helpers ----------------
__device__ __forceinline__ void mma_bf16(float* c, const unsigned* a, const unsigned* b) {
    asm volatile(
        "mma.sync.aligned.m16n8k16.row.col.f32.bf16.bf16.f32 "
        "{%0,%1,%2,%3},{%4,%5,%6,%7},{%8,%9},{%0,%1,%2,%3};\n"
        : "+f"(c[0]), "+f"(c[1]), "+f"(c[2]), "+f"(c[3])
        : "r"(a[0]), "r"(a[1]), "r"(a[2]), "r"(a[3]), "r"(b[0]), "r"(b[1]));
}
__device__ __forceinline__ void ldsm_x4(unsigned* r, const void* p) {
    unsigned a = (unsigned)__cvta_generic_to_shared(p);
    asm volatile("ldmatrix.sync.aligned.m8n8.x4.shared.b16 {%0,%1,%2,%3}, [%4];\n"
                 : "=r"(r[0]), "=r"(r[1]), "=r"(r[2]), "=r"(r[3]) : "r"(a));
}

// ---------------- K0: split conv_w into bf16 hi/lo planes ----------------
__global__ void k0_prep(const float* __restrict__ conv_w) {
    int i = (blockIdx.x * 256 + threadIdx.x) * 4;
#pragma unroll
    for (int j = 0; j < 4; j++) {
        float w = conv_w[i + j];
        __nv_bfloat16 h = __float2bfloat16_rn(w);
        g_whi[i + j] = h;
        g_wlo[i + j] = __float2bfloat16_rn(w - __bfloat162float(h));
    }
}

// ---------------- K12: channel-sum + topk + lnorm + gather (fully fused) ----------------
// grid 128 (one block per n), 1024 threads.
__global__ void __launch_bounds__(1024, 1)
k12_fused(const float* __restrict__ sounds) {
    __shared__ float part[4][SPOS];
    __shared__ float feat[SPOS];
    __shared__ float rval[SPOS];
    __shared__ int   ridx[SPOS];
    __shared__ int   sel[KNODES];
    __shared__ int   rr[KNODES], cc[KNODES];
    __shared__ float Amat[KNODES][KNODES];
    __shared__ float dinv[KNODES];
    __shared__ int   spos[KNODES];
    __shared__ __nv_bfloat162 smh[64][17];
    __shared__ __nv_bfloat162 sml[64][17];

    const int n = blockIdx.x;
    const int tid = threadIdx.x;
    const float* snd_n = sounds + (size_t)n * CIN * SPOS;

    // ---- phase A: channel sum ----
    {
        const int pos = tid & 255, cg = tid >> 8;
        const float* base = snd_n + (size_t)(cg * 512) * SPOS + pos;
        float a[8];
#pragma unroll
        for (int i = 0; i < 8; i++) a[i] = 0.f;
#pragma unroll 2
        for (int c = 0; c < 512; c += 8) {
#pragma unroll
            for (int i = 0; i < 8; i++) a[i] += base[(c + i) * SPOS];
        }
        part[cg][pos] =
            ((a[0] + a[1]) + (a[2] + a[3])) + ((a[4] + a[5]) + (a[6] + a[7]));
    }
    __syncthreads();
    if (tid < 256)
        feat[tid] = part[0][tid] + part[1][tid] + part[2][tid] + part[3][tid];
    __syncthreads();

    // ---- phase B: top-16 (descending, min-index ties) ----
    for (int it = 0; it < KNODES; it++) {
        if (tid < 256) {
            rval[tid] = feat[tid];
            ridx[tid] = tid;
        }
        __syncthreads();
        for (int sstep = 128; sstep > 0; sstep >>= 1) {
            if (tid < sstep) {
                float v2 = rval[tid + sstep];
                int   i2 = ridx[tid + sstep];
                if (v2 > rval[tid] || (v2 == rval[tid] && i2 < ridx[tid])) {
                    rval[tid] = v2;
                    ridx[tid] = i2;
                }
            }
            __syncthreads();
        }
        if (tid == 0) {
            sel[it] = ridx[0];
            feat[ridx[0]] = -3.4e38f;
        }
        __syncthreads();
    }

    // ---- phase C: positions + lnorm ----
    if (tid < KNODES) {
        int p = sel[tid];
        int r = (p < 16) ? 0 : ((p >> 4) - 1);
        int q = p & 15;
        int c = (q == 0) ? 15 : (q - 1);
        rr[tid] = r;
        cc[tid] = c;
        spos[tid] = r * 16 + c;
    }
    __syncthreads();
    if (tid < 256) {
        int i = tid >> 4, j = tid & 15;
        float dr = (float)(rr[i] - rr[j]);
        float dc = (float)(cc[i] - cc[j]);
        Amat[i][j] = expf(-(dr * dr + dc * dc) / (2.0f * (float)KNODES));
    }
    __syncthreads();
    if (tid < KNODES) {
        float s = 0.f;
#pragma unroll
        for (int j = 0; j < KNODES; j++) s += Amat[tid][j];
        dinv[tid] = 1.0f / sqrtf(s);
    }
    __syncthreads();
    if (tid < 256) {
        int i = tid >> 4, j = tid & 15;
        g_lnorm[n * 256 + tid] = Amat[i][j] * dinv[i] * dinv[j];
    }

    // ---- phase D: gather + bf16 split + transpose + coalesced plane writes ----
    // reader: k = tid&15, ci = (tid>>4)&63 -> channels pass*128 + ci*2, +1
    // writer: k2 = tid>>6, c2 = tid&63 -> row n*16+k2, bf162 col pass*64 + c2
    {
        const int k = tid & 15, ci = (tid >> 4) & 63;
        const int k2 = tid >> 6, c2 = tid & 63;
        const float* base = snd_n + spos[k];
        __nv_bfloat162* ahi2 = (__nv_bfloat162*)g_ahi;
        __nv_bfloat162* alo2 = (__nv_bfloat162*)g_alo;
        const size_t rowbase = (size_t)(n * 16 + k2) * (CIN / 2);

        float v0, v1;
        {
            int c = ci * 2;
            v0 = __ldg(&base[(size_t)c * SPOS]);
            v1 = __ldg(&base[(size_t)(c + 1) * SPOS]);
        }
#pragma unroll 1
        for (int pass = 0; pass < 16; pass++) {
            float u0 = v0, u1 = v1;
            if (pass + 1 < 16) {
                int c = (pass + 1) * 128 + ci * 2;
                v0 = __ldg(&base[(size_t)c * SPOS]);
                v1 = __ldg(&base[(size_t)(c + 1) * SPOS]);
            }
            __nv_bfloat16 h0 = __float2bfloat16_rn(u0);
            __nv_bfloat16 h1 = __float2bfloat16_rn(u1);
            __nv_bfloat16 l0 = __float2bfloat16_rn(u0 - __bfloat162float(h0));
            __nv_bfloat16 l1 = __float2bfloat16_rn(u1 - __bfloat162float(h1));
            __syncthreads();   // previous pass's writers done with smem
            smh[ci][k] = __nv_bfloat162(h0, h1);
            sml[ci][k] = __nv_bfloat162(l0, l1);
            __syncthreads();
            size_t o = rowbase + pass * 64 + c2;
            ahi2[o] = smh[c2][k2];
            alo2[o] = sml[c2][k2];
        }
    }
}

// ---------------- K3g: split-bf16 tensor-core GEMM on compact planes ----------------
// grid (32 mt, 8): nt = y&1, ks = y>>1 (K-split 4, chunk 512). 256 threads.
#define KT     32
#define KITERS 16           // 512 / 32
#define APITCH 40
#define BPITCH 40
#define SMB_OFF 0
#define SMA_OFF (2 * 2 * 128 * BPITCH * 2)           // 40960
#define SMEMSZ  (SMA_OFF + 2 * 2 * 64 * APITCH * 2)  // 61440

__global__ void __launch_bounds__(256, 2)
k3g_gemm(void) {
    extern __shared__ __align__(16) char smraw[];
    __nv_bfloat16* Bsm = (__nv_bfloat16*)(smraw + SMB_OFF);
    __nv_bfloat16* Asm = (__nv_bfloat16*)(smraw + SMA_OFF);

    const int tid = threadIdx.x;
    const int mt  = blockIdx.x;
    const int nt  = blockIdx.y & 1;
    const int ks  = blockIdx.y >> 1;
    const int m0  = mt * 64;
    const int ncol0 = nt * 128;
    const int kc0 = ks * 512;

    auto load_tile = [&](int t, int buf) {
        const int k0 = kc0 + t * KT;
        {
            int row = tid >> 2, kq = (tid & 3) * 8;
            cp16(&Asm[((buf * 2 + 0) * 64 + row) * APITCH + kq],
                 &g_ahi[(size_t)(m0 + row) * CIN + k0 + kq]);
            cp16(&Asm[((buf * 2 + 1) * 64 + row) * APITCH + kq],
                 &g_alo[(size_t)(m0 + row) * CIN + k0 + kq]);
        }
#pragma unroll
        for (int i = 0; i < 2; i++) {
            int q = tid + 256 * i;
            int col = q >> 2, kq = (q & 3) * 8;
            cp16(&Bsm[((buf * 2 + 0) * 128 + col) * BPITCH + kq],
                 &g_whi[(size_t)(ncol0 + col) * CIN + k0 + kq]);
            cp16(&Bsm[((buf * 2 + 1) * 128 + col) * BPITCH + kq],
                 &g_wlo[(size_t)(ncol0 + col) * CIN + k0 + kq]);
        }
    };

    const int warp = tid >> 5, lane = tid & 31;
    const int wm = warp & 1, wn = warp >> 1;
    const int mrow0 = wm * 32;
    const int ncb = wn * 32;
    const int aRow = lane & 15, aCol = (lane >> 4) * 8;
    const int bRow = (lane & 7) + ((lane >> 4) & 1) * 8;
    const int bCol = ((lane >> 3) & 1) * 8;

    float acc[2][4][4];
#pragma unroll
    for (int mi = 0; mi < 2; mi++)
#pragma unroll
        for (int nj = 0; nj < 4; nj++)
#pragma unroll
            for (int v = 0; v < 4; v++) acc[mi][nj][v] = 0.f;

    load_tile(0, 0);
    cp_commit();

    for (int t = 0; t < KITERS; t++) {
        const int buf = t & 1;
        cp_wait<0>();
        __syncthreads();
        if (t + 1 < KITERS) {
            load_tile(t + 1, 1 - buf);
            cp_commit();
        }
        const __nv_bfloat16* Ah = Asm + (buf * 2 + 0) * 64 * APITCH;
        const __nv_bfloat16* Al = Asm + (buf * 2 + 1) * 64 * APITCH;
        const __nv_bfloat16* Bh = Bsm + (buf * 2 + 0) * 128 * BPITCH;
        const __nv_bfloat16* Bl = Bsm + (buf * 2 + 1) * 128 * BPITCH;
#pragma unroll
        for (int s16 = 0; s16 < KT; s16 += 16) {
            unsigned ah[2][4], al[2][4], bh[2][4], bl[2][4];
            ldsm_x4(ah[0], &Ah[(mrow0 + aRow) * APITCH + s16 + aCol]);
            ldsm_x4(ah[1], &Ah[(mrow0 + 16 + aRow) * APITCH + s16 + aCol]);
            ldsm_x4(al[0], &Al[(mrow0 + aRow) * APITCH + s16 + aCol]);
            ldsm_x4(al[1], &Al[(mrow0 + 16 + aRow) * APITCH + s16 + aCol]);
            ldsm_x4(bh[0], &Bh[(ncb + bRow) * BPITCH + s16 + bCol]);
            ldsm_x4(bh[1], &Bh[(ncb + 16 + bRow) * BPITCH + s16 + bCol]);
            ldsm_x4(bl[0], &Bl[(ncb + bRow) * BPITCH + s16 + bCol]);
            ldsm_x4(bl[1], &Bl[(ncb + 16 + bRow) * BPITCH + s16 + bCol]);
#pragma unroll
            for (int mi = 0; mi < 2; mi++) {
#pragma unroll
                for (int nj = 0; nj < 4; nj++) {
                    const unsigned* bhf = &bh[nj >> 1][(nj & 1) * 2];
                    const unsigned* blf = &bl[nj >> 1][(nj & 1) * 2];
                    mma_bf16(acc[mi][nj], ah[mi], bhf);
                    mma_bf16(acc[mi][nj], ah[mi], blf);
                    mma_bf16(acc[mi][nj], al[mi], bhf);
                }
            }
        }
    }

    {
        int r = lane >> 2, cq = (lane & 3) * 2;
        float* dst = g_xpart[ks];
#pragma unroll
        for (int mi = 0; mi < 2; mi++) {
#pragma unroll
            for (int nj = 0; nj < 4; nj++) {
                int row0 = m0 + mrow0 + mi * 16 + r;
                int col = ncol0 + ncb + nj * 8 + cq;
                *(float2*)&dst[(size_t)row0 * COUT + col] =
                    make_float2(acc[mi][nj][0], acc[mi][nj][1]);
                *(float2*)&dst[(size_t)(row0 + 8) * COUT + col] =
                    make_float2(acc[mi][nj][2], acc[mi][nj][3]);
            }
        }
    }
}

// ---------------- K3b: sum splits + bias + relu + lnorm mix ----------------
__global__ void k3b_mix(const float* __restrict__ conv_b) {
    __shared__ float L[256];
    int n = blockIdx.x, t = threadIdx.x;
    L[t] = g_lnorm[n * 256 + t];
    float b = conv_b[t];
    float xv[16];
#pragma unroll
    for (int k = 0; k < 16; k++) {
        size_t idx = (size_t)(n * 16 + k) * COUT + t;
        float s = g_xpart[0][idx] + g_xpart[1][idx] + g_xpart[2][idx] +
                  g_xpart[3][idx] + b;
        xv[k] = fmaxf(s, 0.f);
    }
    __syncthreads();
#pragma unroll
    for (int i = 0; i < 16; i++) {
        float y = 0.f;
#pragma unroll
        for (int j = 0; j < 16; j++) y += L[i * 16 + j] * xv[j];
        g_y[(size_t)n * KFC + i * 256 + t] = y;
    }
}

// ---------------- K5: FC GEMM (fp32, k-split x16, 256 blocks) ----------------
__global__ void k5_fc(const float* __restrict__ fc_w) {
    __shared__ float As[2][64][17];
    __shared__ float Bs[2][64][17];
    int tid = threadIdx.x;
    int b = blockIdx.x;
    int ks = b & 15;
    int dt = (b >> 4) & 7;
    int nh = b >> 7;
    int n0 = nh * 64, d0 = dt * 64, k0 = ks * 256;
    int warp = tid >> 5, lane = tid & 31;
    int nr0 = warp * 8;

    auto load_tile = [&](int t, int buf) {
        int kbase = k0 + t * 16;
#pragma unroll
        for (int i = 0; i < 4; i++) {
            int e = tid + 256 * i;
            int nn = e >> 4, kk = e & 15;
            cp4(&As[buf][nn][kk], &g_y[(size_t)(n0 + nn) * KFC + kbase + kk]);
        }
#pragma unroll
        for (int i = 0; i < 4; i++) {
            int e = tid + 256 * i;
            int dd = e >> 4, kk = e & 15;
            cp4(&Bs[buf][dd][kk], &fc_w[(size_t)(d0 + dd) * KFC + kbase + kk]);
        }
    };

    float acc[8][2];
#pragma unroll
    for (int i = 0; i < 8; i++) {
        acc[i][0] = 0.f;
        acc[i][1] = 0.f;
    }

    load_tile(0, 0);
    cp_commit();

    for (int t = 0; t < 16; t++) {
        int buf = t & 1;
        if (t + 1 < 16) {
            load_tile(t + 1, 1 - buf);
            cp_commit();
            cp_wait<1>();
        } else {
            cp_wait<0>();
        }
        __syncthreads();

#pragma unroll
        for (int kk = 0; kk < 16; kk++) {
            float av[8];
#pragma unroll
            for (int i = 0; i < 8; i++) av[i] = As[buf][nr0 + i][kk];
            float b0 = Bs[buf][lane][kk];
            float b1 = Bs[buf][lane + 32][kk];
#pragma unroll
            for (int i = 0; i < 8; i++) {
                acc[i][0] += av[i] * b0;
                acc[i][1] += av[i] * b1;
            }
        }
        __syncthreads();
    }

#pragma unroll
    for (int i = 0; i < 8; i++) {
        size_t base = (size_t)ks * (NBATCH * DOUT) + (size_t)(n0 + nr0 + i) * DOUT + d0;
        g_partial[base + lane] = acc[i][0];
        g_partial[base + lane + 32] = acc[i][1];
    }
}

// ---------------- K6: reduce k-splits + bias ----------------
__global__ void k6_reduce(const float* __restrict__ fc_b, float* __restrict__ out) {
    int idx = blockIdx.x * 256 + threadIdx.x;
    int d = idx & (DOUT - 1);
    float s = fc_b[d];
#pragma unroll
    for (int ks = 0; ks < 16; ks++) s += g_partial[(size_t)ks * (NBATCH * DOUT) + idx];
    out[idx] = s;
}

// ---------------- launch ----------------
extern "C" void kernel_launch(void* const* d_in, const int* in_sizes, int n_in,
                              void* d_out, int out_size) {
    const float* sounds = (const float*)d_in[0];
    const float* conv_w = (const float*)d_in[1];
    const float* conv_b = (const float*)d_in[2];
    const float* fc_w   = (const float*)d_in[3];
    const float* fc_b   = (const float*)d_in[4];
    float* out = (float*)d_out;

    cudaFuncSetAttribute(k3g_gemm, cudaFuncAttributeMaxDynamicSharedMemorySize, SMEMSZ);

    k0_prep<<<512, 256>>>(conv_w);
    k12_fused<<<128, 1024>>>(sounds);
    k3g_gemm<<<dim3(32, 8), 256, SMEMSZ>>>();
    k3b_mix<<<128, 256>>>(conv_b);
    k5_fc<<<256, 256>>>(fc_w);
    k6_reduce<<<256, 256>>>(fc_b, out);
}

// round 8
// speedup vs baseline: 1.9980x; 1.0107x over previous
#include <cuda_runtime.h>
#include <cuda_bf16.h>
#include <cstdint>
#include <math.h>

#define NBATCH 128
#define CIN    2048
#define COUT   256
#define KNODES 16
#define SPOS   256
#define DOUT   512
#define KFC    4096
#define MROWS  2048
#define KSPLIT 4
#define FUSED_BLOCKS 256

// ---------------- device scratch ----------------
__device__ float g_lnorm[NBATCH * KNODES * KNODES];
__device__ float g_y[NBATCH * KNODES * COUT];
__device__ float g_partial[16 * NBATCH * DOUT];
__device__ __nv_bfloat16 g_whi[COUT * CIN];
__device__ __nv_bfloat16 g_wlo[COUT * CIN];
__device__ __nv_bfloat16 g_ahi[MROWS * CIN];
__device__ __nv_bfloat16 g_alo[MROWS * CIN];
__device__ float g_xpart[KSPLIT][MROWS * COUT];
__device__ volatile int g_bar[4];

// ---------------- async copy helpers ----------------
__device__ __forceinline__ void cp4(void* smem, const void* gmem) {
    unsigned int s = (unsigned int)__cvta_generic_to_shared(smem);
    asm volatile("cp.async.ca.shared.global [%0], [%1], 4;\n" :: "r"(s), "l"(gmem));
}
__device__ __forceinline__ void cp16(void* smem, const void* gmem) {
    unsigned int s = (unsigned int)__cvta_generic_to_shared(smem);
    asm volatile("cp.async.cg.shared.global [%0], [%1], 16;\n" :: "r"(s), "l"(gmem));
}
__device__ __forceinline__ void cp_commit() {
    asm volatile("cp.async.commit_group;\n" ::: "memory");
}
template <int N>
__device__ __forceinline__ void cp_wait() {
    asm volatile("cp.async.wait_group %0;\n" :: "n"(N) : "memory");
}

// ---------------- mma helpers ----------------
__device__ __forceinline__ void mma_bf16(float* c, const unsigned* a, const unsigned* b) {
    asm volatile(
        "mma.sync.aligned.m16n8k16.row.col.f32.bf16.bf16.f32 "
        "{%0,%1,%2,%3},{%4,%5,%6,%7},{%8,%9},{%0,%1,%2,%3};\n"
        : "+f"(c[0]), "+f"(c[1]), "+f"(c[2]), "+f"(c[3])
        : "r"(a[0]), "r"(a[1]), "r"(a[2]), "r"(a[3]), "r"(b[0]), "r"(b[1]));
}
__device__ __forceinline__ void ldsm_x4(unsigned* r, const void* p) {
    unsigned a = (unsigned)__cvta_generic_to_shared(p);
    asm volatile("ldmatrix.sync.aligned.m8n8.x4.shared.b16 {%0,%1,%2,%3}, [%4];\n"
                 : "=r"(r[0]), "=r"(r[1]), "=r"(r[2]), "=r"(r[3]) : "r"(a));
}

// ---------------- grid barrier (all blocks resident) ----------------
__device__ __forceinline__ void gbar(int id) {
    __syncthreads();
    __threadfence();
    if (threadIdx.x == 0) {
        atomicAdd((int*)&g_bar[id], 1);
        while (g_bar[id] < FUSED_BLOCKS) __nanosleep(64);
    }
    __syncthreads();
}

// ---------------- K0: split conv_w + reset barriers ----------------
__global__ void k0_prep(const float* __restrict__ conv_w) {
    int i = (blockIdx.x * 256 + threadIdx.x) * 4;
    if (blockIdx.x == 0 && threadIdx.x < 4) g_bar[threadIdx.x] = 0;
#pragma unroll
    for (int j = 0; j < 4; j++) {
        float w = conv_w[i + j];
        __nv_bfloat16 h = __float2bfloat16_rn(w);
        g_whi[i + j] = h;
        g_wlo[i + j] = __float2bfloat16_rn(w - __bfloat162float(h));
    }
}

// ---------------- K12: channel-sum + topk + lnorm + gather (fused) ----------------
__global__ void __launch_bounds__(1024, 1)
k12_fused(const float* __restrict__ sounds) {
    __shared__ float part[4][SPOS];
    __shared__ float feat[SPOS];
    __shared__ float rval[SPOS];
    __shared__ int   ridx[SPOS];
    __shared__ int   sel[KNODES];
    __shared__ int   rr[KNODES], cc[KNODES];
    __shared__ float Amat[KNODES][KNODES];
    __shared__ float dinv[KNODES];
    __shared__ int   spos[KNODES];
    __shared__ __nv_bfloat162 smh[64][17];
    __shared__ __nv_bfloat162 sml[64][17];

    const int n = blockIdx.x;
    const int tid = threadIdx.x;
    const float* snd_n = sounds + (size_t)n * CIN * SPOS;

    {
        const int pos = tid & 255, cg = tid >> 8;
        const float* base = snd_n + (size_t)(cg * 512) * SPOS + pos;
        float a[8];
#pragma unroll
        for (int i = 0; i < 8; i++) a[i] = 0.f;
#pragma unroll 2
        for (int c = 0; c < 512; c += 8) {
#pragma unroll
            for (int i = 0; i < 8; i++) a[i] += base[(c + i) * SPOS];
        }
        part[cg][pos] =
            ((a[0] + a[1]) + (a[2] + a[3])) + ((a[4] + a[5]) + (a[6] + a[7]));
    }
    __syncthreads();
    if (tid < 256)
        feat[tid] = part[0][tid] + part[1][tid] + part[2][tid] + part[3][tid];
    __syncthreads();

    for (int it = 0; it < KNODES; it++) {
        if (tid < 256) {
            rval[tid] = feat[tid];
            ridx[tid] = tid;
        }
        __syncthreads();
        for (int sstep = 128; sstep > 0; sstep >>= 1) {
            if (tid < sstep) {
                float v2 = rval[tid + sstep];
                int   i2 = ridx[tid + sstep];
                if (v2 > rval[tid] || (v2 == rval[tid] && i2 < ridx[tid])) {
                    rval[tid] = v2;
                    ridx[tid] = i2;
                }
            }
            __syncthreads();
        }
        if (tid == 0) {
            sel[it] = ridx[0];
            feat[ridx[0]] = -3.4e38f;
        }
        __syncthreads();
    }

    if (tid < KNODES) {
        int p = sel[tid];
        int r = (p < 16) ? 0 : ((p >> 4) - 1);
        int q = p & 15;
        int c = (q == 0) ? 15 : (q - 1);
        rr[tid] = r;
        cc[tid] = c;
        spos[tid] = r * 16 + c;
    }
    __syncthreads();
    if (tid < 256) {
        int i = tid >> 4, j = tid & 15;
        float dr = (float)(rr[i] - rr[j]);
        float dc = (float)(cc[i] - cc[j]);
        Amat[i][j] = expf(-(dr * dr + dc * dc) / (2.0f * (float)KNODES));
    }
    __syncthreads();
    if (tid < KNODES) {
        float s = 0.f;
#pragma unroll
        for (int j = 0; j < KNODES; j++) s += Amat[tid][j];
        dinv[tid] = 1.0f / sqrtf(s);
    }
    __syncthreads();
    if (tid < 256) {
        int i = tid >> 4, j = tid & 15;
        g_lnorm[n * 256 + tid] = Amat[i][j] * dinv[i] * dinv[j];
    }

    {
        const int k = tid & 15, ci = (tid >> 4) & 63;
        const int k2 = tid >> 6, c2 = tid & 63;
        const float* base = snd_n + spos[k];
        __nv_bfloat162* ahi2 = (__nv_bfloat162*)g_ahi;
        __nv_bfloat162* alo2 = (__nv_bfloat162*)g_alo;
        const size_t rowbase = (size_t)(n * 16 + k2) * (CIN / 2);

        float v0, v1;
        {
            int c = ci * 2;
            v0 = __ldg(&base[(size_t)c * SPOS]);
            v1 = __ldg(&base[(size_t)(c + 1) * SPOS]);
        }
#pragma unroll 1
        for (int pass = 0; pass < 16; pass++) {
            float u0 = v0, u1 = v1;
            if (pass + 1 < 16) {
                int c = (pass + 1) * 128 + ci * 2;
                v0 = __ldg(&base[(size_t)c * SPOS]);
                v1 = __ldg(&base[(size_t)(c + 1) * SPOS]);
            }
            __nv_bfloat16 h0 = __float2bfloat16_rn(u0);
            __nv_bfloat16 h1 = __float2bfloat16_rn(u1);
            __nv_bfloat16 l0 = __float2bfloat16_rn(u0 - __bfloat162float(h0));
            __nv_bfloat16 l1 = __float2bfloat16_rn(u1 - __bfloat162float(h1));
            __syncthreads();
            smh[ci][k] = __nv_bfloat162(h0, h1);
            sml[ci][k] = __nv_bfloat162(l0, l1);
            __syncthreads();
            size_t o = rowbase + pass * 64 + c2;
            ahi2[o] = smh[c2][k2];
            alo2[o] = sml[c2][k2];
        }
    }
}

// ---------------- fused tail: GEMM1 + mix + FC + reduce ----------------
#define KT     32
#define KITERS 16
#define APITCH 40
#define BPITCH 40
#define SMB_OFF 0
#define SMA_OFF (2 * 2 * 128 * BPITCH * 2)           // 40960
#define SMEMSZ  (SMA_OFF + 2 * 2 * 64 * APITCH * 2)  // 61440

__global__ void __launch_bounds__(256, 2)
k_tail(const float* __restrict__ conv_b,
       const float* __restrict__ fc_w,
       const float* __restrict__ fc_b,
       float* __restrict__ out) {
    extern __shared__ __align__(16) char smraw[];
    const int tid = threadIdx.x;
    const int blk = blockIdx.x;
    const int warp = tid >> 5, lane = tid & 31;

    // ================= stage 1: GEMM1 (split-bf16 MMA) =================
    {
        __nv_bfloat16* Bsm = (__nv_bfloat16*)(smraw + SMB_OFF);
        __nv_bfloat16* Asm = (__nv_bfloat16*)(smraw + SMA_OFF);
        const int mt = blk & 31;
        const int nt = (blk >> 5) & 1;
        const int ks = blk >> 6;
        const int m0 = mt * 64;
        const int ncol0 = nt * 128;
        const int kc0 = ks * 512;

        auto load_tile = [&](int t, int buf) {
            const int k0 = kc0 + t * KT;
            {
                int row = tid >> 2, kq = (tid & 3) * 8;
                cp16(&Asm[((buf * 2 + 0) * 64 + row) * APITCH + kq],
                     &g_ahi[(size_t)(m0 + row) * CIN + k0 + kq]);
                cp16(&Asm[((buf * 2 + 1) * 64 + row) * APITCH + kq],
                     &g_alo[(size_t)(m0 + row) * CIN + k0 + kq]);
            }
#pragma unroll
            for (int i = 0; i < 2; i++) {
                int q = tid + 256 * i;
                int col = q >> 2, kq = (q & 3) * 8;
                cp16(&Bsm[((buf * 2 + 0) * 128 + col) * BPITCH + kq],
                     &g_whi[(size_t)(ncol0 + col) * CIN + k0 + kq]);
                cp16(&Bsm[((buf * 2 + 1) * 128 + col) * BPITCH + kq],
                     &g_wlo[(size_t)(ncol0 + col) * CIN + k0 + kq]);
            }
        };

        const int wm = warp & 1, wn = warp >> 1;
        const int mrow0 = wm * 32;
        const int ncb = wn * 32;
        const int aRow = lane & 15, aCol = (lane >> 4) * 8;
        const int bRow = (lane & 7) + ((lane >> 4) & 1) * 8;
        const int bCol = ((lane >> 3) & 1) * 8;

        float acc[2][4][4];
#pragma unroll
        for (int mi = 0; mi < 2; mi++)
#pragma unroll
            for (int nj = 0; nj < 4; nj++)
#pragma unroll
                for (int v = 0; v < 4; v++) acc[mi][nj][v] = 0.f;

        load_tile(0, 0);
        cp_commit();

        for (int t = 0; t < KITERS; t++) {
            const int buf = t & 1;
            cp_wait<0>();
            __syncthreads();
            if (t + 1 < KITERS) {
                load_tile(t + 1, 1 - buf);
                cp_commit();
            }
            const __nv_bfloat16* Ah = Asm + (buf * 2 + 0) * 64 * APITCH;
            const __nv_bfloat16* Al = Asm + (buf * 2 + 1) * 64 * APITCH;
            const __nv_bfloat16* Bh = Bsm + (buf * 2 + 0) * 128 * BPITCH;
            const __nv_bfloat16* Bl = Bsm + (buf * 2 + 1) * 128 * BPITCH;
#pragma unroll
            for (int s16 = 0; s16 < KT; s16 += 16) {
                unsigned ah[2][4], al[2][4], bh[2][4], bl[2][4];
                ldsm_x4(ah[0], &Ah[(mrow0 + aRow) * APITCH + s16 + aCol]);
                ldsm_x4(ah[1], &Ah[(mrow0 + 16 + aRow) * APITCH + s16 + aCol]);
                ldsm_x4(al[0], &Al[(mrow0 + aRow) * APITCH + s16 + aCol]);
                ldsm_x4(al[1], &Al[(mrow0 + 16 + aRow) * APITCH + s16 + aCol]);
                ldsm_x4(bh[0], &Bh[(ncb + bRow) * BPITCH + s16 + bCol]);
                ldsm_x4(bh[1], &Bh[(ncb + 16 + bRow) * BPITCH + s16 + bCol]);
                ldsm_x4(bl[0], &Bl[(ncb + bRow) * BPITCH + s16 + bCol]);
                ldsm_x4(bl[1], &Bl[(ncb + 16 + bRow) * BPITCH + s16 + bCol]);
#pragma unroll
                for (int mi = 0; mi < 2; mi++) {
#pragma unroll
                    for (int nj = 0; nj < 4; nj++) {
                        const unsigned* bhf = &bh[nj >> 1][(nj & 1) * 2];
                        const unsigned* blf = &bl[nj >> 1][(nj & 1) * 2];
                        mma_bf16(acc[mi][nj], ah[mi], bhf);
                        mma_bf16(acc[mi][nj], ah[mi], blf);
                        mma_bf16(acc[mi][nj], al[mi], bhf);
                    }
                }
            }
        }

        {
            int r = lane >> 2, cq = (lane & 3) * 2;
            float* dst = g_xpart[ks];
#pragma unroll
            for (int mi = 0; mi < 2; mi++) {
#pragma unroll
                for (int nj = 0; nj < 4; nj++) {
                    int row0 = m0 + mrow0 + mi * 16 + r;
                    int col = ncol0 + ncb + nj * 8 + cq;
                    *(float2*)&dst[(size_t)row0 * COUT + col] =
                        make_float2(acc[mi][nj][0], acc[mi][nj][1]);
                    *(float2*)&dst[(size_t)(row0 + 8) * COUT + col] =
                        make_float2(acc[mi][nj][2], acc[mi][nj][3]);
                }
            }
        }
    }

    gbar(0);

    // ================= stage 2: sum splits + bias + relu + lnorm mix =================
    if (blk < NBATCH) {
        float* L = (float*)smraw;
        const int n = blk;
        L[tid] = g_lnorm[n * 256 + tid];
        float b = conv_b[tid];
        float xv[16];
#pragma unroll
        for (int k = 0; k < 16; k++) {
            size_t idx = (size_t)(n * 16 + k) * COUT + tid;
            float s = g_xpart[0][idx] + g_xpart[1][idx] + g_xpart[2][idx] +
                      g_xpart[3][idx] + b;
            xv[k] = fmaxf(s, 0.f);
        }
        __syncthreads();
#pragma unroll
        for (int i = 0; i < 16; i++) {
            float y = 0.f;
#pragma unroll
            for (int j = 0; j < 16; j++) y += L[i * 16 + j] * xv[j];
            g_y[(size_t)n * KFC + i * 256 + tid] = y;
        }
    }

    gbar(1);

    // ================= stage 3: FC GEMM (fp32, k-split x16) =================
    {
        float (*As)[64][17] = (float (*)[64][17])smraw;
        float (*Bs)[64][17] = (float (*)[64][17])(smraw + 2 * 64 * 17 * 4);
        const int ks = blk & 15;
        const int dt = (blk >> 4) & 7;
        const int nh = blk >> 7;
        const int n0 = nh * 64, d0 = dt * 64, k0 = ks * 256;
        const int nr0 = warp * 8;

        auto load_tile = [&](int t, int buf) {
            int kbase = k0 + t * 16;
#pragma unroll
            for (int i = 0; i < 4; i++) {
                int e = tid + 256 * i;
                int nn = e >> 4, kk = e & 15;
                cp4(&As[buf][nn][kk], &g_y[(size_t)(n0 + nn) * KFC + kbase + kk]);
            }
#pragma unroll
            for (int i = 0; i < 4; i++) {
                int e = tid + 256 * i;
                int dd = e >> 4, kk = e & 15;
                cp4(&Bs[buf][dd][kk], &fc_w[(size_t)(d0 + dd) * KFC + kbase + kk]);
            }
        };

        float acc[8][2];
#pragma unroll
        for (int i = 0; i < 8; i++) {
            acc[i][0] = 0.f;
            acc[i][1] = 0.f;
        }

        load_tile(0, 0);
        cp_commit();

        for (int t = 0; t < 16; t++) {
            int buf = t & 1;
            if (t + 1 < 16) {
                load_tile(t + 1, 1 - buf);
                cp_commit();
                cp_wait<1>();
            } else {
                cp_wait<0>();
            }
            __syncthreads();

#pragma unroll
            for (int kk = 0; kk < 16; kk++) {
                float av[8];
#pragma unroll
                for (int i = 0; i < 8; i++) av[i] = As[buf][nr0 + i][kk];
                float b0 = Bs[buf][lane][kk];
                float b1 = Bs[buf][lane + 32][kk];
#pragma unroll
                for (int i = 0; i < 8; i++) {
                    acc[i][0] += av[i] * b0;
                    acc[i][1] += av[i] * b1;
                }
            }
            __syncthreads();
        }

#pragma unroll
        for (int i = 0; i < 8; i++) {
            size_t base =
                (size_t)ks * (NBATCH * DOUT) + (size_t)(n0 + nr0 + i) * DOUT + d0;
            g_partial[base + lane] = acc[i][0];
            g_partial[base + lane + 32] = acc[i][1];
        }
    }

    gbar(2);

    // ================= stage 4: reduce k-splits + bias =================
    {
        int idx = blk * 256 + tid;
        int d = idx & (DOUT - 1);
        float s = fc_b[d];
#pragma unroll
        for (int ks = 0; ks < 16; ks++)
            s += g_partial[(size_t)ks * (NBATCH * DOUT) + idx];
        out[idx] = s;
    }
}

// ---------------- launch ----------------
extern "C" void kernel_launch(void* const* d_in, const int* in_sizes, int n_in,
                              void* d_out, int out_size) {
    const float* sounds = (const float*)d_in[0];
    const float* conv_w = (const float*)d_in[1];
    const float* conv_b = (const float*)d_in[2];
    const float* fc_w   = (const float*)d_in[3];
    const float* fc_b   = (const float*)d_in[4];
    float* out = (float*)d_out;

    cudaFuncSetAttribute(k_tail, cudaFuncAttributeMaxDynamicSharedMemorySize, SMEMSZ);

    k0_prep<<<512, 256>>>(conv_w);
    k12_fused<<<128, 1024>>>(sounds);
    k_tail<<<FUSED_BLOCKS, 256, SMEMSZ>>>(conv_b, fc_w, fc_b, out);
}

// round 9
// speedup vs baseline: 2.0554x; 1.0287x over previous
#include <cuda_runtime.h>
#include <cuda_bf16.h>
#include <cstdint>
#include <math.h>

#define NBATCH 128
#define CIN    2048
#define COUT   256
#define KNODES 16
#define SPOS   256
#define DOUT   512
#define KFC    4096
#define MROWS  2048
#define KSPLIT 4
#define FUSED_BLOCKS 256

// ---------------- device scratch ----------------
__device__ float g_lnorm[NBATCH * KNODES * KNODES];
__device__ float g_y[NBATCH * KNODES * COUT];
__device__ float g_partial[16 * NBATCH * DOUT];
__device__ __nv_bfloat16 g_whi[COUT * CIN];
__device__ __nv_bfloat16 g_wlo[COUT * CIN];
__device__ __nv_bfloat16 g_ahi[MROWS * CIN];
__device__ __nv_bfloat16 g_alo[MROWS * CIN];
__device__ float g_xpart[KSPLIT][MROWS * COUT];
__device__ volatile int g_bar[4];

// ---------------- async copy helpers ----------------
__device__ __forceinline__ void cp4(void* smem, const void* gmem) {
    unsigned int s = (unsigned int)__cvta_generic_to_shared(smem);
    asm volatile("cp.async.ca.shared.global [%0], [%1], 4;\n" :: "r"(s), "l"(gmem));
}
__device__ __forceinline__ void cp16(void* smem, const void* gmem) {
    unsigned int s = (unsigned int)__cvta_generic_to_shared(smem);
    asm volatile("cp.async.cg.shared.global [%0], [%1], 16;\n" :: "r"(s), "l"(gmem));
}
__device__ __forceinline__ void cp_commit() {
    asm volatile("cp.async.commit_group;\n" ::: "memory");
}
template <int N>
__device__ __forceinline__ void cp_wait() {
    asm volatile("cp.async.wait_group %0;\n" :: "n"(N) : "memory");
}
__device__ __forceinline__ void pf_l2(const void* p) {
    asm volatile("prefetch.global.L2 [%0];" :: "l"(p));
}

// ---------------- mma helpers ----------------
__device__ __forceinline__ void mma_bf16(float* c, const unsigned* a, const unsigned* b) {
    asm volatile(
        "mma.sync.aligned.m16n8k16.row.col.f32.bf16.bf16.f32 "
        "{%0,%1,%2,%3},{%4,%5,%6,%7},{%8,%9},{%0,%1,%2,%3};\n"
        : "+f"(c[0]), "+f"(c[1]), "+f"(c[2]), "+f"(c[3])
        : "r"(a[0]), "r"(a[1]), "r"(a[2]), "r"(a[3]), "r"(b[0]), "r"(b[1]));
}
__device__ __forceinline__ void ldsm_x4(unsigned* r, const void* p) {
    unsigned a = (unsigned)__cvta_generic_to_shared(p);
    asm volatile("ldmatrix.sync.aligned.m8n8.x4.shared.b16 {%0,%1,%2,%3}, [%4];\n"
                 : "=r"(r[0]), "=r"(r[1]), "=r"(r[2]), "=r"(r[3]) : "r"(a));
}

// ---------------- grid barrier ----------------
__device__ __forceinline__ void gbar(int id) {
    __syncthreads();
    __threadfence();
    if (threadIdx.x == 0) {
        atomicAdd((int*)&g_bar[id], 1);
        while (g_bar[id] < FUSED_BLOCKS) __nanosleep(64);
    }
    __syncthreads();
}

// ---------------- K12: w-split + channel-sum + topk + lnorm + gather ----------------
// grid 128 (one block per n), 1024 threads.
__global__ void __launch_bounds__(1024, 1)
k12_fused(const float* __restrict__ sounds, const float* __restrict__ conv_w) {
    __shared__ float part[4][SPOS];
    __shared__ float feat[SPOS];
    __shared__ float rval[SPOS];
    __shared__ int   ridx[SPOS];
    __shared__ int   sel[KNODES];
    __shared__ int   rr[KNODES], cc[KNODES];
    __shared__ float Amat[KNODES][KNODES];
    __shared__ float dinv[KNODES];
    __shared__ int   spos[KNODES];
    __shared__ __nv_bfloat162 smh[2][64][17];
    __shared__ __nv_bfloat162 sml[2][64][17];

    const int n = blockIdx.x;
    const int tid = threadIdx.x;
    const float* snd_n = sounds + (size_t)n * CIN * SPOS;

    // ---- phase 0: barrier reset + conv_w hi/lo split (was k0) ----
    if (n == 0 && tid < 4) g_bar[tid] = 0;
    {
        int i = (n * 1024 + tid) * 4;
        float4 w4 = *(const float4*)&conv_w[i];
        float w[4] = {w4.x, w4.y, w4.z, w4.w};
#pragma unroll
        for (int j = 0; j < 4; j++) {
            __nv_bfloat16 h = __float2bfloat16_rn(w[j]);
            g_whi[i + j] = h;
            g_wlo[i + j] = __float2bfloat16_rn(w[j] - __bfloat162float(h));
        }
    }

    // ---- phase A: channel sum ----
    {
        const int pos = tid & 255, cg = tid >> 8;
        const float* base = snd_n + (size_t)(cg * 512) * SPOS + pos;
        float a[8];
#pragma unroll
        for (int i = 0; i < 8; i++) a[i] = 0.f;
#pragma unroll 2
        for (int c = 0; c < 512; c += 8) {
#pragma unroll
            for (int i = 0; i < 8; i++) a[i] += base[(c + i) * SPOS];
        }
        part[cg][pos] =
            ((a[0] + a[1]) + (a[2] + a[3])) + ((a[4] + a[5]) + (a[6] + a[7]));
    }
    __syncthreads();
    if (tid < 256)
        feat[tid] = part[0][tid] + part[1][tid] + part[2][tid] + part[3][tid];
    __syncthreads();

    // ---- phase B: top-16 (descending, min-index ties) ----
    for (int it = 0; it < KNODES; it++) {
        if (tid < 256) {
            rval[tid] = feat[tid];
            ridx[tid] = tid;
        }
        __syncthreads();
        for (int sstep = 128; sstep > 0; sstep >>= 1) {
            if (tid < sstep) {
                float v2 = rval[tid + sstep];
                int   i2 = ridx[tid + sstep];
                if (v2 > rval[tid] || (v2 == rval[tid] && i2 < ridx[tid])) {
                    rval[tid] = v2;
                    ridx[tid] = i2;
                }
            }
            __syncthreads();
        }
        if (tid == 0) {
            sel[it] = ridx[0];
            feat[ridx[0]] = -3.4e38f;
        }
        __syncthreads();
    }

    // ---- phase C: positions + lnorm ----
    if (tid < KNODES) {
        int p = sel[tid];
        int r = (p < 16) ? 0 : ((p >> 4) - 1);
        int q = p & 15;
        int c = (q == 0) ? 15 : (q - 1);
        rr[tid] = r;
        cc[tid] = c;
        spos[tid] = r * 16 + c;
    }
    __syncthreads();
    if (tid < 256) {
        int i = tid >> 4, j = tid & 15;
        float dr = (float)(rr[i] - rr[j]);
        float dc = (float)(cc[i] - cc[j]);
        Amat[i][j] = expf(-(dr * dr + dc * dc) / (2.0f * (float)KNODES));
    }
    __syncthreads();
    if (tid < KNODES) {
        float s = 0.f;
#pragma unroll
        for (int j = 0; j < KNODES; j++) s += Amat[tid][j];
        dinv[tid] = 1.0f / sqrtf(s);
    }
    __syncthreads();
    if (tid < 256) {
        int i = tid >> 4, j = tid & 15;
        g_lnorm[n * 256 + tid] = Amat[i][j] * dinv[i] * dinv[j];
    }

    // ---- phase D: gather + bf16 split + transpose (double-buffered, 1 sync/pass) ----
    {
        const int k = tid & 15, ci = (tid >> 4) & 63;
        const int k2 = tid >> 6, c2 = tid & 63;
        const float* base = snd_n + spos[k];
        __nv_bfloat162* ahi2 = (__nv_bfloat162*)g_ahi;
        __nv_bfloat162* alo2 = (__nv_bfloat162*)g_alo;
        const size_t rowbase = (size_t)(n * 16 + k2) * (CIN / 2);

        float v0, v1;
        {
            int c = ci * 2;
            v0 = __ldg(&base[(size_t)c * SPOS]);
            v1 = __ldg(&base[(size_t)(c + 1) * SPOS]);
        }
#pragma unroll 1
        for (int pass = 0; pass < 16; pass++) {
            const int pb = pass & 1;
            float u0 = v0, u1 = v1;
            if (pass + 1 < 16) {
                int c = (pass + 1) * 128 + ci * 2;
                v0 = __ldg(&base[(size_t)c * SPOS]);
                v1 = __ldg(&base[(size_t)(c + 1) * SPOS]);
            }
            __nv_bfloat16 h0 = __float2bfloat16_rn(u0);
            __nv_bfloat16 h1 = __float2bfloat16_rn(u1);
            __nv_bfloat16 l0 = __float2bfloat16_rn(u0 - __bfloat162float(h0));
            __nv_bfloat16 l1 = __float2bfloat16_rn(u1 - __bfloat162float(h1));
            smh[pb][ci][k] = __nv_bfloat162(h0, h1);
            sml[pb][ci][k] = __nv_bfloat162(l0, l1);
            __syncthreads();
            size_t o = rowbase + pass * 64 + c2;
            ahi2[o] = smh[pb][c2][k2];
            alo2[o] = sml[pb][c2][k2];
        }
    }
}

// ---------------- fused tail: GEMM1 + mix + FC + reduce ----------------
#define KT     32
#define KITERS 16
#define APITCH 40
#define BPITCH 40
#define SMB_OFF 0
#define SMA_OFF (2 * 2 * 128 * BPITCH * 2)           // 40960
#define SMEMSZ  (SMA_OFF + 2 * 2 * 64 * APITCH * 2)  // 61440

__global__ void __launch_bounds__(256, 2)
k_tail(const float* __restrict__ conv_b,
       const float* __restrict__ fc_w,
       const float* __restrict__ fc_b,
       float* __restrict__ out) {
    extern __shared__ __align__(16) char smraw[];
    const int tid = threadIdx.x;
    const int blk = blockIdx.x;
    const int warp = tid >> 5, lane = tid & 31;

    // ================= stage 1: GEMM1 (split-bf16 MMA) =================
    {
        // prefetch fc_w (8 MB) into L2 for stage 3: one 128B line per thread
        pf_l2((const char*)fc_w + ((size_t)blk * 256 + tid) * 128);

        __nv_bfloat16* Bsm = (__nv_bfloat16*)(smraw + SMB_OFF);
        __nv_bfloat16* Asm = (__nv_bfloat16*)(smraw + SMA_OFF);
        const int mt = blk & 31;
        const int nt = (blk >> 5) & 1;
        const int ks = blk >> 6;
        const int m0 = mt * 64;
        const int ncol0 = nt * 128;
        const int kc0 = ks * 512;

        auto load_tile = [&](int t, int buf) {
            const int k0 = kc0 + t * KT;
            {
                int row = tid >> 2, kq = (tid & 3) * 8;
                cp16(&Asm[((buf * 2 + 0) * 64 + row) * APITCH + kq],
                     &g_ahi[(size_t)(m0 + row) * CIN + k0 + kq]);
                cp16(&Asm[((buf * 2 + 1) * 64 + row) * APITCH + kq],
                     &g_alo[(size_t)(m0 + row) * CIN + k0 + kq]);
            }
#pragma unroll
            for (int i = 0; i < 2; i++) {
                int q = tid + 256 * i;
                int col = q >> 2, kq = (q & 3) * 8;
                cp16(&Bsm[((buf * 2 + 0) * 128 + col) * BPITCH + kq],
                     &g_whi[(size_t)(ncol0 + col) * CIN + k0 + kq]);
                cp16(&Bsm[((buf * 2 + 1) * 128 + col) * BPITCH + kq],
                     &g_wlo[(size_t)(ncol0 + col) * CIN + k0 + kq]);
            }
        };

        const int wm = warp & 1, wn = warp >> 1;
        const int mrow0 = wm * 32;
        const int ncb = wn * 32;
        const int aRow = lane & 15, aCol = (lane >> 4) * 8;
        const int bRow = (lane & 7) + ((lane >> 4) & 1) * 8;
        const int bCol = ((lane >> 3) & 1) * 8;

        float acc[2][4][4];
#pragma unroll
        for (int mi = 0; mi < 2; mi++)
#pragma unroll
            for (int nj = 0; nj < 4; nj++)
#pragma unroll
                for (int v = 0; v < 4; v++) acc[mi][nj][v] = 0.f;

        load_tile(0, 0);
        cp_commit();

        for (int t = 0; t < KITERS; t++) {
            const int buf = t & 1;
            if (t + 1 < KITERS) {
                load_tile(t + 1, 1 - buf);   // issue BEFORE waiting on tile t
                cp_commit();
                cp_wait<1>();
            } else {
                cp_wait<0>();
            }
            __syncthreads();
            const __nv_bfloat16* Ah = Asm + (buf * 2 + 0) * 64 * APITCH;
            const __nv_bfloat16* Al = Asm + (buf * 2 + 1) * 64 * APITCH;
            const __nv_bfloat16* Bh = Bsm + (buf * 2 + 0) * 128 * BPITCH;
            const __nv_bfloat16* Bl = Bsm + (buf * 2 + 1) * 128 * BPITCH;
#pragma unroll
            for (int s16 = 0; s16 < KT; s16 += 16) {
                unsigned ah[2][4], al[2][4], bh[2][4], bl[2][4];
                ldsm_x4(ah[0], &Ah[(mrow0 + aRow) * APITCH + s16 + aCol]);
                ldsm_x4(ah[1], &Ah[(mrow0 + 16 + aRow) * APITCH + s16 + aCol]);
                ldsm_x4(al[0], &Al[(mrow0 + aRow) * APITCH + s16 + aCol]);
                ldsm_x4(al[1], &Al[(mrow0 + 16 + aRow) * APITCH + s16 + aCol]);
                ldsm_x4(bh[0], &Bh[(ncb + bRow) * BPITCH + s16 + bCol]);
                ldsm_x4(bh[1], &Bh[(ncb + 16 + bRow) * BPITCH + s16 + bCol]);
                ldsm_x4(bl[0], &Bl[(ncb + bRow) * BPITCH + s16 + bCol]);
                ldsm_x4(bl[1], &Bl[(ncb + 16 + bRow) * BPITCH + s16 + bCol]);
#pragma unroll
                for (int mi = 0; mi < 2; mi++) {
#pragma unroll
                    for (int nj = 0; nj < 4; nj++) {
                        const unsigned* bhf = &bh[nj >> 1][(nj & 1) * 2];
                        const unsigned* blf = &bl[nj >> 1][(nj & 1) * 2];
                        mma_bf16(acc[mi][nj], ah[mi], bhf);
                        mma_bf16(acc[mi][nj], ah[mi], blf);
                        mma_bf16(acc[mi][nj], al[mi], bhf);
                    }
                }
            }
            __syncthreads();   // all warps done reading buf before it is reloaded
        }

        {
            int r = lane >> 2, cq = (lane & 3) * 2;
            float* dst = g_xpart[ks];
#pragma unroll
            for (int mi = 0; mi < 2; mi++) {
#pragma unroll
                for (int nj = 0; nj < 4; nj++) {
                    int row0 = m0 + mrow0 + mi * 16 + r;
                    int col = ncol0 + ncb + nj * 8 + cq;
                    *(float2*)&dst[(size_t)row0 * COUT + col] =
                        make_float2(acc[mi][nj][0], acc[mi][nj][1]);
                    *(float2*)&dst[(size_t)(row0 + 8) * COUT + col] =
                        make_float2(acc[mi][nj][2], acc[mi][nj][3]);
                }
            }
        }
    }

    gbar(0);

    // ================= stage 2: sum splits + bias + relu + lnorm mix =================
    if (blk < NBATCH) {
        float* L = (float*)smraw;
        const int n = blk;
        L[tid] = g_lnorm[n * 256 + tid];
        float b = conv_b[tid];
        float xv[16];
#pragma unroll
        for (int k = 0; k < 16; k++) {
            size_t idx = (size_t)(n * 16 + k) * COUT + tid;
            float s = g_xpart[0][idx] + g_xpart[1][idx] + g_xpart[2][idx] +
                      g_xpart[3][idx] + b;
            xv[k] = fmaxf(s, 0.f);
        }
        __syncthreads();
#pragma unroll
        for (int i = 0; i < 16; i++) {
            float y = 0.f;
#pragma unroll
            for (int j = 0; j < 16; j++) y += L[i * 16 + j] * xv[j];
            g_y[(size_t)n * KFC + i * 256 + tid] = y;
        }
    }

    gbar(1);

    // ================= stage 3: FC GEMM (fp32, k-split x16) =================
    {
        float (*As)[64][17] = (float (*)[64][17])smraw;
        float (*Bs)[64][17] = (float (*)[64][17])(smraw + 2 * 64 * 17 * 4);
        const int ks = blk & 15;
        const int dt = (blk >> 4) & 7;
        const int nh = blk >> 7;
        const int n0 = nh * 64, d0 = dt * 64, k0 = ks * 256;
        const int nr0 = warp * 8;

        auto load_tile = [&](int t, int buf) {
            int kbase = k0 + t * 16;
#pragma unroll
            for (int i = 0; i < 4; i++) {
                int e = tid + 256 * i;
                int nn = e >> 4, kk = e & 15;
                cp4(&As[buf][nn][kk], &g_y[(size_t)(n0 + nn) * KFC + kbase + kk]);
            }
#pragma unroll
            for (int i = 0; i < 4; i++) {
                int e = tid + 256 * i;
                int dd = e >> 4, kk = e & 15;
                cp4(&Bs[buf][dd][kk], &fc_w[(size_t)(d0 + dd) * KFC + kbase + kk]);
            }
        };

        float acc[8][2];
#pragma unroll
        for (int i = 0; i < 8; i++) {
            acc[i][0] = 0.f;
            acc[i][1] = 0.f;
        }

        load_tile(0, 0);
        cp_commit();

        for (int t = 0; t < 16; t++) {
            int buf = t & 1;
            if (t + 1 < 16) {
                load_tile(t + 1, 1 - buf);
                cp_commit();
                cp_wait<1>();
            } else {
                cp_wait<0>();
            }
            __syncthreads();

#pragma unroll
            for (int kk = 0; kk < 16; kk++) {
                float av[8];
#pragma unroll
                for (int i = 0; i < 8; i++) av[i] = As[buf][nr0 + i][kk];
                float b0 = Bs[buf][lane][kk];
                float b1 = Bs[buf][lane + 32][kk];
#pragma unroll
                for (int i = 0; i < 8; i++) {
                    acc[i][0] += av[i] * b0;
                    acc[i][1] += av[i] * b1;
                }
            }
            __syncthreads();
        }

#pragma unroll
        for (int i = 0; i < 8; i++) {
            size_t base =
                (size_t)ks * (NBATCH * DOUT) + (size_t)(n0 + nr0 + i) * DOUT + d0;
            g_partial[base + lane] = acc[i][0];
            g_partial[base + lane + 32] = acc[i][1];
        }
    }

    gbar(2);

    // ================= stage 4: reduce k-splits + bias =================
    {
        int idx = blk * 256 + tid;
        int d = idx & (DOUT - 1);
        float s = fc_b[d];
#pragma unroll
        for (int ks = 0; ks < 16; ks++)
            s += g_partial[(size_t)ks * (NBATCH * DOUT) + idx];
        out[idx] = s;
    }
}

// ---------------- launch ----------------
extern "C" void kernel_launch(void* const* d_in, const int* in_sizes, int n_in,
                              void* d_out, int out_size) {
    const float* sounds = (const float*)d_in[0];
    const float* conv_w = (const float*)d_in[1];
    const float* conv_b = (const float*)d_in[2];
    const float* fc_w   = (const float*)d_in[3];
    const float* fc_b   = (const float*)d_in[4];
    float* out = (float*)d_out;

    cudaFuncSetAttribute(k_tail, cudaFuncAttributeMaxDynamicSharedMemorySize, SMEMSZ);

    k12_fused<<<128, 1024>>>(sounds, conv_w);
    k_tail<<<FUSED_BLOCKS, 256, SMEMSZ>>>(conv_b, fc_w, fc_b, out);
}

// round 10
// speedup vs baseline: 2.0836x; 1.0137x over previous
#include <cuda_runtime.h>
#include <cuda_bf16.h>
#include <cstdint>
#include <math.h>

#define NBATCH 128
#define CIN    2048
#define COUT   256
#define KNODES 16
#define SPOS   256
#define DOUT   512
#define KFC    4096
#define MROWS  2048
#define KSPLIT 4
#define FUSED_BLOCKS 256
#define FC_KSPLIT 32

// ---------------- device scratch ----------------
__device__ float g_lnorm[NBATCH * KNODES * KNODES];
__device__ __nv_bfloat16 g_whi[COUT * CIN];
__device__ __nv_bfloat16 g_wlo[COUT * CIN];
__device__ __nv_bfloat16 g_fwhi[DOUT * KFC];
__device__ __nv_bfloat16 g_fwlo[DOUT * KFC];
__device__ __nv_bfloat16 g_ahi[MROWS * CIN];
__device__ __nv_bfloat16 g_alo[MROWS * CIN];
__device__ __nv_bfloat16 g_yhi[NBATCH * KFC];
__device__ __nv_bfloat16 g_ylo[NBATCH * KFC];
__device__ float g_xpart[KSPLIT][MROWS * COUT];
__device__ float g_part2[FC_KSPLIT][NBATCH * DOUT];
__device__ volatile int g_bar[4];

// ---------------- async copy helpers ----------------
__device__ __forceinline__ void cp16(void* smem, const void* gmem) {
    unsigned int s = (unsigned int)__cvta_generic_to_shared(smem);
    asm volatile("cp.async.cg.shared.global [%0], [%1], 16;\n" :: "r"(s), "l"(gmem));
}
__device__ __forceinline__ void cp_commit() {
    asm volatile("cp.async.commit_group;\n" ::: "memory");
}
template <int N>
__device__ __forceinline__ void cp_wait() {
    asm volatile("cp.async.wait_group %0;\n" :: "n"(N) : "memory");
}
__device__ __forceinline__ void pf_l2(const void* p) {
    asm volatile("prefetch.global.L2 [%0];" :: "l"(p));
}

// ---------------- mma helpers ----------------
__device__ __forceinline__ void mma_bf16(float* c, const unsigned* a, const unsigned* b) {
    asm volatile(
        "mma.sync.aligned.m16n8k16.row.col.f32.bf16.bf16.f32 "
        "{%0,%1,%2,%3},{%4,%5,%6,%7},{%8,%9},{%0,%1,%2,%3};\n"
        : "+f"(c[0]), "+f"(c[1]), "+f"(c[2]), "+f"(c[3])
        : "r"(a[0]), "r"(a[1]), "r"(a[2]), "r"(a[3]), "r"(b[0]), "r"(b[1]));
}
__device__ __forceinline__ void ldsm_x4(unsigned* r, const void* p) {
    unsigned a = (unsigned)__cvta_generic_to_shared(p);
    asm volatile("ldmatrix.sync.aligned.m8n8.x4.shared.b16 {%0,%1,%2,%3}, [%4];\n"
                 : "=r"(r[0]), "=r"(r[1]), "=r"(r[2]), "=r"(r[3]) : "r"(a));
}

// ---------------- grid barrier ----------------
__device__ __forceinline__ void gbar(int id) {
    __syncthreads();
    __threadfence();
    if (threadIdx.x == 0) {
        atomicAdd((int*)&g_bar[id], 1);
        while (g_bar[id] < FUSED_BLOCKS) __nanosleep(64);
    }
    __syncthreads();
}

// ---------------- shared GEMM tile geometry ----------------
#define KT     32
#define APITCH 40
#define BPITCH 40
#define SMB_OFF 0
#define SMA_OFF (2 * 2 * 128 * BPITCH * 2)           // 40960
#define SMEMSZ  (SMA_OFF + 2 * 2 * 64 * APITCH * 2)  // 61440

// ---------------- K12: w-splits + channel-sum + topk + lnorm + gather ----------------
// grid 128 (one block per n), 1024 threads.
__global__ void __launch_bounds__(1024, 1)
k12_fused(const float* __restrict__ sounds, const float* __restrict__ conv_w,
          const float* __restrict__ fc_w) {
    __shared__ float part[4][SPOS];
    __shared__ float feat[SPOS];
    __shared__ int   sel[KNODES];
    __shared__ int   rr[KNODES], cc[KNODES];
    __shared__ float Amat[KNODES][KNODES];
    __shared__ float dinv[KNODES];
    __shared__ int   spos[KNODES];
    __shared__ __nv_bfloat162 smh[2][64][17];
    __shared__ __nv_bfloat162 sml[2][64][17];

    const int n = blockIdx.x;
    const int tid = threadIdx.x;
    const float* snd_n = sounds + (size_t)n * CIN * SPOS;

    // ---- phase 0: barrier reset + conv_w split + fc_w split ----
    if (n == 0 && tid < 4) g_bar[tid] = 0;
    {
        int i = (n * 1024 + tid) * 4;
        float4 w4 = *(const float4*)&conv_w[i];
        float w[4] = {w4.x, w4.y, w4.z, w4.w};
#pragma unroll
        for (int j = 0; j < 4; j++) {
            __nv_bfloat16 h = __float2bfloat16_rn(w[j]);
            g_whi[i + j] = h;
            g_wlo[i + j] = __float2bfloat16_rn(w[j] - __bfloat162float(h));
        }
    }
    {
        int base = (n * 1024 + tid) * 16;
#pragma unroll
        for (int q = 0; q < 4; q++) {
            int i = base + q * 4;
            float4 w4 = *(const float4*)&fc_w[i];
            float w[4] = {w4.x, w4.y, w4.z, w4.w};
#pragma unroll
            for (int j = 0; j < 4; j++) {
                __nv_bfloat16 h = __float2bfloat16_rn(w[j]);
                g_fwhi[i + j] = h;
                g_fwlo[i + j] = __float2bfloat16_rn(w[j] - __bfloat162float(h));
            }
        }
    }

    // ---- phase A: channel sum ----
    {
        const int pos = tid & 255, cg = tid >> 8;
        const float* base = snd_n + (size_t)(cg * 512) * SPOS + pos;
        float a[8];
#pragma unroll
        for (int i = 0; i < 8; i++) a[i] = 0.f;
#pragma unroll 2
        for (int c = 0; c < 512; c += 8) {
#pragma unroll
            for (int i = 0; i < 8; i++) a[i] += base[(c + i) * SPOS];
        }
        part[cg][pos] =
            ((a[0] + a[1]) + (a[2] + a[3])) + ((a[4] + a[5]) + (a[6] + a[7]));
    }
    __syncthreads();
    if (tid < 256)
        feat[tid] = part[0][tid] + part[1][tid] + part[2][tid] + part[3][tid];
    __syncthreads();

    // ---- phase B: top-16 via single-warp register reduction ----
    // key = sortable(value) << 32 | (255 - idx): max key == max value, tie -> min idx
    if (tid < 32) {
        float vals[8];
#pragma unroll
        for (int j = 0; j < 8; j++) vals[j] = feat[tid * 8 + j];
#pragma unroll 1
        for (int it = 0; it < KNODES; it++) {
            unsigned long long k = 0ull;
#pragma unroll
            for (int j = 0; j < 8; j++) {
                unsigned fb = __float_as_uint(vals[j]);
                fb = (fb & 0x80000000u) ? ~fb : (fb | 0x80000000u);
                unsigned long long key =
                    ((unsigned long long)fb << 32) | (unsigned)(255 - (tid * 8 + j));
                if (key > k) k = key;
            }
#pragma unroll
            for (int s = 16; s > 0; s >>= 1) {
                unsigned long long o = __shfl_down_sync(0xffffffffu, k, s);
                if (o > k) k = o;
            }
            k = __shfl_sync(0xffffffffu, k, 0);
            int idx = 255 - (int)(k & 0xffffffffu);
            if (tid == (idx >> 3)) {
                int m = idx & 7;
#pragma unroll
                for (int j = 0; j < 8; j++)
                    if (j == m) vals[j] = -3.4e38f;
            }
            if (tid == 0) sel[it] = idx;
        }
    }
    __syncthreads();

    // ---- phase C: positions + lnorm ----
    if (tid < KNODES) {
        int p = sel[tid];
        int r = (p < 16) ? 0 : ((p >> 4) - 1);
        int q = p & 15;
        int c = (q == 0) ? 15 : (q - 1);
        rr[tid] = r;
        cc[tid] = c;
        spos[tid] = r * 16 + c;
    }
    __syncthreads();
    if (tid < 256) {
        int i = tid >> 4, j = tid & 15;
        float dr = (float)(rr[i] - rr[j]);
        float dc = (float)(cc[i] - cc[j]);
        Amat[i][j] = expf(-(dr * dr + dc * dc) / (2.0f * (float)KNODES));
    }
    __syncthreads();
    if (tid < KNODES) {
        float s = 0.f;
#pragma unroll
        for (int j = 0; j < KNODES; j++) s += Amat[tid][j];
        dinv[tid] = 1.0f / sqrtf(s);
    }
    __syncthreads();
    if (tid < 256) {
        int i = tid >> 4, j = tid & 15;
        g_lnorm[n * 256 + tid] = Amat[i][j] * dinv[i] * dinv[j];
    }

    // ---- phase D: gather + bf16 split + transpose (prefetch depth 2) ----
    {
        const int k = tid & 15, ci = (tid >> 4) & 63;
        const int k2 = tid >> 6, c2 = tid & 63;
        const float* base = snd_n + spos[k];
        __nv_bfloat162* ahi2 = (__nv_bfloat162*)g_ahi;
        __nv_bfloat162* alo2 = (__nv_bfloat162*)g_alo;
        const size_t rowbase = (size_t)(n * 16 + k2) * (CIN / 2);

        float v[2][2];
#pragma unroll
        for (int p = 0; p < 2; p++) {
            int c = p * 128 + ci * 2;
            v[p][0] = __ldg(&base[(size_t)c * SPOS]);
            v[p][1] = __ldg(&base[(size_t)(c + 1) * SPOS]);
        }
#pragma unroll 1
        for (int pass = 0; pass < 16; pass++) {
            const int pb = pass & 1;
            float u0 = v[pb][0], u1 = v[pb][1];
            if (pass + 2 < 16) {
                int c = (pass + 2) * 128 + ci * 2;
                v[pb][0] = __ldg(&base[(size_t)c * SPOS]);
                v[pb][1] = __ldg(&base[(size_t)(c + 1) * SPOS]);
            }
            __nv_bfloat16 h0 = __float2bfloat16_rn(u0);
            __nv_bfloat16 h1 = __float2bfloat16_rn(u1);
            __nv_bfloat16 l0 = __float2bfloat16_rn(u0 - __bfloat162float(h0));
            __nv_bfloat16 l1 = __float2bfloat16_rn(u1 - __bfloat162float(h1));
            smh[pb][ci][k] = __nv_bfloat162(h0, h1);
            sml[pb][ci][k] = __nv_bfloat162(l0, l1);
            __syncthreads();
            size_t o = rowbase + pass * 64 + c2;
            ahi2[o] = smh[pb][c2][k2];
            alo2[o] = sml[pb][c2][k2];
        }
    }
}

// ---------------- fused tail: GEMM1 + mix + FC-MMA + reduce ----------------
__global__ void __launch_bounds__(256, 2)
k_tail(const float* __restrict__ conv_b,
       const float* __restrict__ fc_b,
       float* __restrict__ out) {
    extern __shared__ __align__(16) char smraw[];
    const int tid = threadIdx.x;
    const int blk = blockIdx.x;
    const int warp = tid >> 5, lane = tid & 31;

    __nv_bfloat16* Bsm = (__nv_bfloat16*)(smraw + SMB_OFF);
    __nv_bfloat16* Asm = (__nv_bfloat16*)(smraw + SMA_OFF);

    const int wm = warp & 1, wn = warp >> 1;   // 2 x 4 warp grid
    const int mrow0 = wm * 32;
    const int ncb = wn * 32;
    const int aRow = lane & 15, aCol = (lane >> 4) * 8;
    const int bRow = (lane & 7) + ((lane >> 4) & 1) * 8;
    const int bCol = ((lane >> 3) & 1) * 8;

    // ================= stage 1: GEMM1 (split-bf16 MMA, K-split 4) =================
    {
        // prefetch fc_w bf16 planes (8 MB) into L2 for stage 3
        {
            size_t off = ((size_t)blk * 128 + (tid & 127)) * 128;
            if (tid < 128) pf_l2((const char*)g_fwhi + off);
            else           pf_l2((const char*)g_fwlo + off);
        }
        const int mt = blk & 31;
        const int nt = (blk >> 5) & 1;
        const int ks = blk >> 6;
        const int m0 = mt * 64;
        const int ncol0 = nt * 128;
        const int kc0 = ks * 512;
        const int KITERS = 16;

        auto load_tile = [&](int t, int buf) {
            const int k0 = kc0 + t * KT;
            {
                int row = tid >> 2, kq = (tid & 3) * 8;
                cp16(&Asm[((buf * 2 + 0) * 64 + row) * APITCH + kq],
                     &g_ahi[(size_t)(m0 + row) * CIN + k0 + kq]);
                cp16(&Asm[((buf * 2 + 1) * 64 + row) * APITCH + kq],
                     &g_alo[(size_t)(m0 + row) * CIN + k0 + kq]);
            }
#pragma unroll
            for (int i = 0; i < 2; i++) {
                int q = tid + 256 * i;
                int col = q >> 2, kq = (q & 3) * 8;
                cp16(&Bsm[((buf * 2 + 0) * 128 + col) * BPITCH + kq],
                     &g_whi[(size_t)(ncol0 + col) * CIN + k0 + kq]);
                cp16(&Bsm[((buf * 2 + 1) * 128 + col) * BPITCH + kq],
                     &g_wlo[(size_t)(ncol0 + col) * CIN + k0 + kq]);
            }
        };

        float acc[2][4][4];
#pragma unroll
        for (int mi = 0; mi < 2; mi++)
#pragma unroll
            for (int nj = 0; nj < 4; nj++)
#pragma unroll
                for (int v = 0; v < 4; v++) acc[mi][nj][v] = 0.f;

        load_tile(0, 0);
        cp_commit();

        for (int t = 0; t < KITERS; t++) {
            const int buf = t & 1;
            if (t + 1 < KITERS) {
                load_tile(t + 1, 1 - buf);
                cp_commit();
                cp_wait<1>();
            } else {
                cp_wait<0>();
            }
            __syncthreads();
            const __nv_bfloat16* Ah = Asm + (buf * 2 + 0) * 64 * APITCH;
            const __nv_bfloat16* Al = Asm + (buf * 2 + 1) * 64 * APITCH;
            const __nv_bfloat16* Bh = Bsm + (buf * 2 + 0) * 128 * BPITCH;
            const __nv_bfloat16* Bl = Bsm + (buf * 2 + 1) * 128 * BPITCH;
#pragma unroll
            for (int s16 = 0; s16 < KT; s16 += 16) {
                unsigned ah[2][4], al[2][4], bh[2][4], bl[2][4];
                ldsm_x4(ah[0], &Ah[(mrow0 + aRow) * APITCH + s16 + aCol]);
                ldsm_x4(ah[1], &Ah[(mrow0 + 16 + aRow) * APITCH + s16 + aCol]);
                ldsm_x4(al[0], &Al[(mrow0 + aRow) * APITCH + s16 + aCol]);
                ldsm_x4(al[1], &Al[(mrow0 + 16 + aRow) * APITCH + s16 + aCol]);
                ldsm_x4(bh[0], &Bh[(ncb + bRow) * BPITCH + s16 + bCol]);
                ldsm_x4(bh[1], &Bh[(ncb + 16 + bRow) * BPITCH + s16 + bCol]);
                ldsm_x4(bl[0], &Bl[(ncb + bRow) * BPITCH + s16 + bCol]);
                ldsm_x4(bl[1], &Bl[(ncb + 16 + bRow) * BPITCH + s16 + bCol]);
#pragma unroll
                for (int mi = 0; mi < 2; mi++) {
#pragma unroll
                    for (int nj = 0; nj < 4; nj++) {
                        const unsigned* bhf = &bh[nj >> 1][(nj & 1) * 2];
                        const unsigned* blf = &bl[nj >> 1][(nj & 1) * 2];
                        mma_bf16(acc[mi][nj], ah[mi], bhf);
                        mma_bf16(acc[mi][nj], ah[mi], blf);
                        mma_bf16(acc[mi][nj], al[mi], bhf);
                    }
                }
            }
            __syncthreads();
        }

        {
            int r = lane >> 2, cq = (lane & 3) * 2;
            float* dst = g_xpart[ks];
#pragma unroll
            for (int mi = 0; mi < 2; mi++) {
#pragma unroll
                for (int nj = 0; nj < 4; nj++) {
                    int row0 = m0 + mrow0 + mi * 16 + r;
                    int col = ncol0 + ncb + nj * 8 + cq;
                    *(float2*)&dst[(size_t)row0 * COUT + col] =
                        make_float2(acc[mi][nj][0], acc[mi][nj][1]);
                    *(float2*)&dst[(size_t)(row0 + 8) * COUT + col] =
                        make_float2(acc[mi][nj][2], acc[mi][nj][3]);
                }
            }
        }
    }

    gbar(0);

    // ================= stage 2: sum splits + bias + relu + lnorm mix -> y hi/lo =================
    if (blk < NBATCH) {
        float* L = (float*)smraw;
        const int n = blk;
        L[tid] = g_lnorm[n * 256 + tid];
        float b = conv_b[tid];
        float xv[16];
#pragma unroll
        for (int k = 0; k < 16; k++) {
            size_t idx = (size_t)(n * 16 + k) * COUT + tid;
            float s = g_xpart[0][idx] + g_xpart[1][idx] + g_xpart[2][idx] +
                      g_xpart[3][idx] + b;
            xv[k] = fmaxf(s, 0.f);
        }
        __syncthreads();
#pragma unroll
        for (int i = 0; i < 16; i++) {
            float y = 0.f;
#pragma unroll
            for (int j = 0; j < 16; j++) y += L[i * 16 + j] * xv[j];
            __nv_bfloat16 h = __float2bfloat16_rn(y);
            size_t o = (size_t)n * KFC + i * 256 + tid;
            g_yhi[o] = h;
            g_ylo[o] = __float2bfloat16_rn(y - __bfloat162float(h));
        }
    }

    gbar(1);

    // ================= stage 3: FC GEMM (split-bf16 MMA, K-split 32) =================
    {
        const int mt = blk & 1;
        const int nt = (blk >> 1) & 3;
        const int ks = blk >> 3;            // 0..31
        const int m0 = mt * 64;
        const int ncol0 = nt * 128;
        const int kc0 = ks * 128;
        const int KITERS = 4;

        auto load_tile = [&](int t, int buf) {
            const int k0 = kc0 + t * KT;
            {
                int row = tid >> 2, kq = (tid & 3) * 8;
                cp16(&Asm[((buf * 2 + 0) * 64 + row) * APITCH + kq],
                     &g_yhi[(size_t)(m0 + row) * KFC + k0 + kq]);
                cp16(&Asm[((buf * 2 + 1) * 64 + row) * APITCH + kq],
                     &g_ylo[(size_t)(m0 + row) * KFC + k0 + kq]);
            }
#pragma unroll
            for (int i = 0; i < 2; i++) {
                int q = tid + 256 * i;
                int col = q >> 2, kq = (q & 3) * 8;
                cp16(&Bsm[((buf * 2 + 0) * 128 + col) * BPITCH + kq],
                     &g_fwhi[(size_t)(ncol0 + col) * KFC + k0 + kq]);
                cp16(&Bsm[((buf * 2 + 1) * 128 + col) * BPITCH + kq],
                     &g_fwlo[(size_t)(ncol0 + col) * KFC + k0 + kq]);
            }
        };

        float acc[2][4][4];
#pragma unroll
        for (int mi = 0; mi < 2; mi++)
#pragma unroll
            for (int nj = 0; nj < 4; nj++)
#pragma unroll
                for (int v = 0; v < 4; v++) acc[mi][nj][v] = 0.f;

        load_tile(0, 0);
        cp_commit();

        for (int t = 0; t < KITERS; t++) {
            const int buf = t & 1;
            if (t + 1 < KITERS) {
                load_tile(t + 1, 1 - buf);
                cp_commit();
                cp_wait<1>();
            } else {
                cp_wait<0>();
            }
            __syncthreads();
            const __nv_bfloat16* Ah = Asm + (buf * 2 + 0) * 64 * APITCH;
            const __nv_bfloat16* Al = Asm + (buf * 2 + 1) * 64 * APITCH;
            const __nv_bfloat16* Bh = Bsm + (buf * 2 + 0) * 128 * BPITCH;
            const __nv_bfloat16* Bl = Bsm + (buf * 2 + 1) * 128 * BPITCH;
#pragma unroll
            for (int s16 = 0; s16 < KT; s16 += 16) {
                unsigned ah[2][4], al[2][4], bh[2][4], bl[2][4];
                ldsm_x4(ah[0], &Ah[(mrow0 + aRow) * APITCH + s16 + aCol]);
                ldsm_x4(ah[1], &Ah[(mrow0 + 16 + aRow) * APITCH + s16 + aCol]);
                ldsm_x4(al[0], &Al[(mrow0 + aRow) * APITCH + s16 + aCol]);
                ldsm_x4(al[1], &Al[(mrow0 + 16 + aRow) * APITCH + s16 + aCol]);
                ldsm_x4(bh[0], &Bh[(ncb + bRow) * BPITCH + s16 + bCol]);
                ldsm_x4(bh[1], &Bh[(ncb + 16 + bRow) * BPITCH + s16 + bCol]);
                ldsm_x4(bl[0], &Bl[(ncb + bRow) * BPITCH + s16 + bCol]);
                ldsm_x4(bl[1], &Bl[(ncb + 16 + bRow) * BPITCH + s16 + bCol]);
#pragma unroll
                for (int mi = 0; mi < 2; mi++) {
#pragma unroll
                    for (int nj = 0; nj < 4; nj++) {
                        const unsigned* bhf = &bh[nj >> 1][(nj & 1) * 2];
                        const unsigned* blf = &bl[nj >> 1][(nj & 1) * 2];
                        mma_bf16(acc[mi][nj], ah[mi], bhf);
                        mma_bf16(acc[mi][nj], ah[mi], blf);
                        mma_bf16(acc[mi][nj], al[mi], bhf);
                    }
                }
            }
            __syncthreads();
        }

        {
            int r = lane >> 2, cq = (lane & 3) * 2;
            float* dst = g_part2[ks];
#pragma unroll
            for (int mi = 0; mi < 2; mi++) {
#pragma unroll
                for (int nj = 0; nj < 4; nj++) {
                    int row0 = m0 + mrow0 + mi * 16 + r;
                    int col = ncol0 + ncb + nj * 8 + cq;
                    *(float2*)&dst[(size_t)row0 * DOUT + col] =
                        make_float2(acc[mi][nj][0], acc[mi][nj][1]);
                    *(float2*)&dst[(size_t)(row0 + 8) * DOUT + col] =
                        make_float2(acc[mi][nj][2], acc[mi][nj][3]);
                }
            }
        }
    }

    gbar(2);

    // ================= stage 4: reduce 32 k-splits + bias =================
    {
        int idx = blk * 256 + tid;      // 65536 = 128*512
        int d = idx & (DOUT - 1);
        float s = fc_b[d];
#pragma unroll
        for (int ks = 0; ks < FC_KSPLIT; ks++)
            s += g_part2[ks][idx];
        out[idx] = s;
    }
}

// ---------------- launch ----------------
extern "C" void kernel_launch(void* const* d_in, const int* in_sizes, int n_in,
                              void* d_out, int out_size) {
    const float* sounds = (const float*)d_in[0];
    const float* conv_w = (const float*)d_in[1];
    const float* conv_b = (const float*)d_in[2];
    const float* fc_w   = (const float*)d_in[3];
    const float* fc_b   = (const float*)d_in[4];
    float* out = (float*)d_out;

    cudaFuncSetAttribute(k_tail, cudaFuncAttributeMaxDynamicSharedMemorySize, SMEMSZ);

    k12_fused<<<128, 1024>>>(sounds, conv_w, fc_w);
    k_tail<<<FUSED_BLOCKS, 256, SMEMSZ>>>(conv_b, fc_b, out);
}